// round 2
// baseline (speedup 1.0000x reference)
#include <cuda_runtime.h>
#include <cuda_bf16.h>
#include <cstdint>

// Problem constants (fixed by the dataset)
#define NN      50000
#define IN_C    128
#define HID     256
#define OUT_C   40
#define NLAYERS 4
#define NGROUPS 2
#define GC      128
#define NEDGES  600000
#define LN_EPS  1e-5f

// Scratch (device globals: allocation-free)
__device__ float g_h[(size_t)NN * HID];   // node features [N,256]
__device__ float g_a[(size_t)NN * HID];   // LN+ReLU activations
__device__ float g_z[(size_t)NN * GC];    // conv GEMM output [N,128]
__device__ int   g_src[NEDGES];
__device__ int   g_dst[NEDGES];
__device__ int   g_is64;

// ---------------------------------------------------------------------------
// Detect whether edge_index buffer is int64 or int32.
// If int64 little-endian with values in [0, 50000), every odd 32-bit word of
// the buffer is 0. If int32, odd words are random indices (mostly nonzero).
// ---------------------------------------------------------------------------
__global__ void detect_idx_kernel(const int* __restrict__ ei32)
{
    __shared__ int nz;
    if (threadIdx.x == 0) nz = 0;
    __syncthreads();
    int bad = 0;
    for (int i = threadIdx.x; i < 2048; i += blockDim.x)
        if (ei32[2 * i + 1] != 0) bad = 1;
    if (bad) atomicOr(&nz, 1);
    __syncthreads();
    if (threadIdx.x == 0) g_is64 = (nz == 0) ? 1 : 0;
}

__global__ __launch_bounds__(256) void convert_idx_kernel(const void* __restrict__ ei)
{
    int e = blockIdx.x * blockDim.x + threadIdx.x;
    if (e >= NEDGES) return;
    if (g_is64) {
        const long long* p = (const long long*)ei;
        g_src[e] = (int)p[e];
        g_dst[e] = (int)p[NEDGES + e];
    } else {
        const int* p = (const int*)ei;
        g_src[e] = p[e];
        g_dst[e] = p[NEDGES + e];
    }
}

// ---------------------------------------------------------------------------
// GEMM: C[nrows, *] (+= bias) = A[nrows, K] @ W[K, ldw], 128x128 tile / block,
// 256 threads, 8x8 per-thread microtile, K-tile 16.
// ---------------------------------------------------------------------------
__global__ __launch_bounds__(256) void gemm_kernel(
    const float* __restrict__ A, const float* __restrict__ W,
    const float* __restrict__ bias, float* __restrict__ C,
    int nrows, int K, int ldw, int ldc)
{
    __shared__ float As[16][128];
    __shared__ float Bs[16][128];

    const int tid = threadIdx.x;
    const int rowblk = blockIdx.x * 128;
    const int colblk = blockIdx.y * 128;
    const int trow = (tid >> 4) * 8;
    const int tcol = (tid & 15) * 8;

    float acc[8][8];
#pragma unroll
    for (int i = 0; i < 8; i++)
#pragma unroll
        for (int j = 0; j < 8; j++) acc[i][j] = 0.f;

    for (int kt = 0; kt < K; kt += 16) {
#pragma unroll
        for (int i = 0; i < 2; i++) {
            int q = tid + i * 256;
            int r = q >> 2;
            int k4 = (q & 3) * 4;
            int grow = rowblk + r;
            float4 v = make_float4(0.f, 0.f, 0.f, 0.f);
            if (grow < nrows)
                v = *(const float4*)(A + (size_t)grow * K + kt + k4);
            As[k4 + 0][r] = v.x;
            As[k4 + 1][r] = v.y;
            As[k4 + 2][r] = v.z;
            As[k4 + 3][r] = v.w;
        }
#pragma unroll
        for (int i = 0; i < 2; i++) {
            int q = tid + i * 256;
            int kk = q >> 5;
            int c4 = (q & 31) * 4;
            float4 v = *(const float4*)(W + (size_t)(kt + kk) * ldw + colblk + c4);
            *(float4*)&Bs[kk][c4] = v;
        }
        __syncthreads();

#pragma unroll
        for (int kk = 0; kk < 16; kk++) {
            float ra[8], rb[8];
#pragma unroll
            for (int i = 0; i < 8; i++) ra[i] = As[kk][trow + i];
#pragma unroll
            for (int j = 0; j < 8; j++) rb[j] = Bs[kk][tcol + j];
#pragma unroll
            for (int i = 0; i < 8; i++)
#pragma unroll
                for (int j = 0; j < 8; j++)
                    acc[i][j] = fmaf(ra[i], rb[j], acc[i][j]);
        }
        __syncthreads();
    }

#pragma unroll
    for (int i = 0; i < 8; i++) {
        int grow = rowblk + trow + i;
        if (grow >= nrows) break;
#pragma unroll
        for (int j = 0; j < 8; j += 4) {
            float4 v;
            v.x = acc[i][j + 0];
            v.y = acc[i][j + 1];
            v.z = acc[i][j + 2];
            v.w = acc[i][j + 3];
            if (bias != nullptr) {
                v.x += bias[colblk + tcol + j + 0];
                v.y += bias[colblk + tcol + j + 1];
                v.z += bias[colblk + tcol + j + 2];
                v.w += bias[colblk + tcol + j + 3];
            }
            *(float4*)(C + (size_t)grow * ldc + colblk + tcol + j) = v;
        }
    }
}

// ---------------------------------------------------------------------------
// LayerNorm + ReLU over 128 cols of h (row stride 256, col offset colofs).
// One warp per row.
// ---------------------------------------------------------------------------
__global__ __launch_bounds__(256) void ln_relu128_kernel(
    const float* __restrict__ h, int colofs,
    const float* __restrict__ gamma, const float* __restrict__ beta,
    float* __restrict__ out)
{
    int row = blockIdx.x * 8 + (threadIdx.x >> 5);
    int lane = threadIdx.x & 31;
    if (row >= NN) return;

    float4 v = ((const float4*)(h + (size_t)row * HID + colofs))[lane];
    float s  = v.x + v.y + v.z + v.w;
    float sq = v.x * v.x + v.y * v.y + v.z * v.z + v.w * v.w;
#pragma unroll
    for (int o = 16; o; o >>= 1) {
        s  += __shfl_xor_sync(0xffffffffu, s, o);
        sq += __shfl_xor_sync(0xffffffffu, sq, o);
    }
    float mu  = s * (1.f / 128.f);
    float var = sq * (1.f / 128.f) - mu * mu;
    float rs  = rsqrtf(var + LN_EPS);

    float4 gm = ((const float4*)gamma)[lane];
    float4 bt = ((const float4*)beta)[lane];
    float4 o;
    o.x = fmaxf((v.x - mu) * rs * gm.x + bt.x, 0.f);
    o.y = fmaxf((v.y - mu) * rs * gm.y + bt.y, 0.f);
    o.z = fmaxf((v.z - mu) * rs * gm.z + bt.z, 0.f);
    o.w = fmaxf((v.w - mu) * rs * gm.w + bt.w, 0.f);
    ((float4*)(out + (size_t)row * GC))[lane] = o;
}

// ---------------------------------------------------------------------------
// Final LayerNorm + ReLU over full 256-wide rows of h -> out[N,256]
// ---------------------------------------------------------------------------
__global__ __launch_bounds__(256) void ln_relu256_kernel(
    const float* __restrict__ h,
    const float* __restrict__ gamma, const float* __restrict__ beta,
    float* __restrict__ out)
{
    int row = blockIdx.x * 8 + (threadIdx.x >> 5);
    int lane = threadIdx.x & 31;
    if (row >= NN) return;

    const float4* p = (const float4*)(h + (size_t)row * HID);
    float4 v0 = p[lane];
    float4 v1 = p[lane + 32];
    float s  = v0.x + v0.y + v0.z + v0.w + v1.x + v1.y + v1.z + v1.w;
    float sq = v0.x * v0.x + v0.y * v0.y + v0.z * v0.z + v0.w * v0.w
             + v1.x * v1.x + v1.y * v1.y + v1.z * v1.z + v1.w * v1.w;
#pragma unroll
    for (int o = 16; o; o >>= 1) {
        s  += __shfl_xor_sync(0xffffffffu, s, o);
        sq += __shfl_xor_sync(0xffffffffu, sq, o);
    }
    float mu  = s * (1.f / 256.f);
    float var = sq * (1.f / 256.f) - mu * mu;
    float rs  = rsqrtf(var + LN_EPS);

    float4 g0 = ((const float4*)gamma)[lane];
    float4 g1 = ((const float4*)gamma)[lane + 32];
    float4 b0 = ((const float4*)beta)[lane];
    float4 b1 = ((const float4*)beta)[lane + 32];
    float4 o0, o1;
    o0.x = fmaxf((v0.x - mu) * rs * g0.x + b0.x, 0.f);
    o0.y = fmaxf((v0.y - mu) * rs * g0.y + b0.y, 0.f);
    o0.z = fmaxf((v0.z - mu) * rs * g0.z + b0.z, 0.f);
    o0.w = fmaxf((v0.w - mu) * rs * g0.w + b0.w, 0.f);
    o1.x = fmaxf((v1.x - mu) * rs * g1.x + b1.x, 0.f);
    o1.y = fmaxf((v1.y - mu) * rs * g1.y + b1.y, 0.f);
    o1.z = fmaxf((v1.z - mu) * rs * g1.z + b1.z, 0.f);
    o1.w = fmaxf((v1.w - mu) * rs * g1.w + b1.w, 0.f);
    float4* q = (float4*)(out + (size_t)row * HID);
    q[lane]      = o0;
    q[lane + 32] = o1;
}

// ---------------------------------------------------------------------------
// h[:, colofs:colofs+128] += conv_b  (pre-scatter bias add)
// ---------------------------------------------------------------------------
__global__ __launch_bounds__(256) void bias_add_kernel(
    float* __restrict__ h, int colofs, const float* __restrict__ b)
{
    int idx = blockIdx.x * blockDim.x + threadIdx.x;
    if (idx >= NN * GC) return;
    int r = idx >> 7;
    int c = idx & 127;
    h[(size_t)r * HID + colofs + c] += b[c];
}

// ---------------------------------------------------------------------------
// Edge scatter: h[dst, colofs + c] += w_e * z[src, c]   (one warp per edge)
// ---------------------------------------------------------------------------
__global__ __launch_bounds__(256) void scatter_kernel(
    const float* __restrict__ ew,
    const float* __restrict__ z, float* __restrict__ h, int colofs)
{
    int e = (int)((blockIdx.x * (unsigned)blockDim.x + threadIdx.x) >> 5);
    int lane = threadIdx.x & 31;
    if (e >= NEDGES) return;
    int src = g_src[e];
    int dst = g_dst[e];
    float w = ew[e];
    float4 v = ((const float4*)(z + (size_t)src * GC))[lane];
    float* hp = h + (size_t)dst * HID + colofs + lane * 4;
    atomicAdd(hp + 0, w * v.x);
    atomicAdd(hp + 1, w * v.y);
    atomicAdd(hp + 2, w * v.z);
    atomicAdd(hp + 3, w * v.w);
}

// ---------------------------------------------------------------------------
// lin2: out[N,40] = f[N,256] @ W[256,40] + b. One warp per row.
// ---------------------------------------------------------------------------
__global__ __launch_bounds__(256) void lin2_kernel(
    const float* __restrict__ f, const float* __restrict__ W,
    const float* __restrict__ b, float* __restrict__ out)
{
    __shared__ float ws[OUT_C * HID];  // [c][k], 40 KB
    int tid = threadIdx.x;
    for (int i = tid; i < OUT_C * HID; i += 256) {
        int c = i >> 8;
        int k = i & 255;
        ws[i] = W[k * OUT_C + c];
    }
    __syncthreads();

    int row = blockIdx.x * 8 + (tid >> 5);
    int lane = tid & 31;
    if (row >= NN) return;

    const float4* fp = (const float4*)(f + (size_t)row * HID);
    float4 a = fp[lane];
    float4 bb = fp[lane + 32];
    int k0 = lane * 4;
#pragma unroll 4
    for (int c = 0; c < OUT_C; c++) {
        const float* wc = ws + c * HID;
        float p = a.x * wc[k0] + a.y * wc[k0 + 1] + a.z * wc[k0 + 2] + a.w * wc[k0 + 3]
                + bb.x * wc[128 + k0] + bb.y * wc[128 + k0 + 1]
                + bb.z * wc[128 + k0 + 2] + bb.w * wc[128 + k0 + 3];
#pragma unroll
        for (int o = 16; o; o >>= 1) p += __shfl_xor_sync(0xffffffffu, p, o);
        if (lane == 0) out[(size_t)row * OUT_C + c] = p + b[c];
    }
}

// ---------------------------------------------------------------------------
extern "C" void kernel_launch(void* const* d_in, const int* in_sizes, int n_in,
                              void* d_out, int out_size)
{
    const float* x       = (const float*)d_in[0];
    const void*  ei      = d_in[1];                 // int32 OR int64, detected on device
    const float* ew      = (const float*)d_in[2];
    const float* lin1_w  = (const float*)d_in[3];
    const float* lin1_b  = (const float*)d_in[4];
    const float* lin2_w  = (const float*)d_in[5];
    const float* lin2_b  = (const float*)d_in[6];
    const float* norm_g  = (const float*)d_in[7];
    const float* norm_b  = (const float*)d_in[8];
    const float* conv_w  = (const float*)d_in[9];
    const float* conv_b  = (const float*)d_in[10];
    const float* fnorm_g = (const float*)d_in[11];
    const float* fnorm_b = (const float*)d_in[12];
    float*       out     = (float*)d_out;

    float *h, *a, *z;
    cudaGetSymbolAddress((void**)&h, g_h);
    cudaGetSymbolAddress((void**)&a, g_a);
    cudaGetSymbolAddress((void**)&z, g_z);

    const int GEMM_BX   = (NN + 127) / 128;         // 391
    const int LN_BLKS   = NN / 8;                   // 6250
    const int BIAS_BLKS = (NN * GC + 255) / 256;
    const int SC_BLKS   = (NEDGES * 32) / 256;      // exact
    const int CV_BLKS   = (NEDGES + 255) / 256;

    // Decode edge indices (dtype-agnostic)
    detect_idx_kernel<<<1, 256>>>((const int*)ei);
    convert_idx_kernel<<<CV_BLKS, 256>>>(ei);

    // lin1: h = x @ lin1_w + lin1_b   [N,256]
    gemm_kernel<<<dim3(GEMM_BX, 2), 256>>>(x, lin1_w, lin1_b, h, NN, IN_C, HID, HID);

    for (int l = 0; l < NLAYERS; l++) {
        for (int g = 0; g < NGROUPS; g++) {
            int in_ofs  = (g == 0) ? GC : 0;   // y_in: prev group's columns
            int out_ofs = g * GC;              // write into group g's columns
            int bidx = l * NGROUPS + g;

            ln_relu128_kernel<<<LN_BLKS, 256>>>(
                h, in_ofs, norm_g + (size_t)bidx * GC, norm_b + (size_t)bidx * GC, a);
            gemm_kernel<<<dim3(GEMM_BX, 1), 256>>>(
                a, conv_w + (size_t)bidx * GC * GC, nullptr, z, NN, GC, GC, GC);
            bias_add_kernel<<<BIAS_BLKS, 256>>>(h, out_ofs, conv_b + (size_t)bidx * GC);
            scatter_kernel<<<SC_BLKS, 256>>>(ew, z, h, out_ofs);
        }
    }

    // final LN+ReLU over 256, then lin2
    ln_relu256_kernel<<<LN_BLKS, 256>>>(h, fnorm_g, fnorm_b, a);
    lin2_kernel<<<LN_BLKS, 256>>>(a, lin2_w, lin2_b, out);
}

// round 3
// speedup vs baseline: 2.1046x; 2.1046x over previous
#include <cuda_runtime.h>
#include <cuda_bf16.h>
#include <cstdint>

#define NN      50000
#define IN_C    128
#define HID     256
#define OUT_C   40
#define NLAYERS 4
#define NGROUPS 2
#define GC      128
#define NEDGES  600000
#define LN_EPS  1e-5f

// Scratch (device globals: allocation-free)
__device__ float  g_h[(size_t)NN * HID];     // node features [N,256]
__device__ float  g_z[(size_t)NN * GC];      // conv GEMM output [N,128]
__device__ float2 g_stats[NN];               // per-row (mu, rsigma) for next LN
__device__ int    g_src[NEDGES];
__device__ int    g_dst[NEDGES];
__device__ int    g_cnt[NN];                 // dst histogram
__device__ int    g_cur[NN];                 // fill cursors
__device__ int    g_off[NN + 1];             // CSR offsets
__device__ int2   g_csr[NEDGES];             // (src, bitcast weight) sorted by dst
__device__ int    g_is64;

// ---------------------------------------------------------------------------
// Edge-index dtype detection (int64 vs int32): int64 LE with values < 50000
// has all odd 32-bit words zero.
// ---------------------------------------------------------------------------
__global__ void detect_idx_kernel(const int* __restrict__ ei32)
{
    __shared__ int nz;
    if (threadIdx.x == 0) nz = 0;
    __syncthreads();
    int bad = 0;
    for (int i = threadIdx.x; i < 2048; i += blockDim.x)
        if (ei32[2 * i + 1] != 0) bad = 1;
    if (bad) atomicOr(&nz, 1);
    __syncthreads();
    if (threadIdx.x == 0) g_is64 = (nz == 0) ? 1 : 0;
}

__global__ __launch_bounds__(256) void convert_idx_kernel(const void* __restrict__ ei)
{
    int e = blockIdx.x * blockDim.x + threadIdx.x;
    if (e >= NEDGES) return;
    if (g_is64) {
        const long long* p = (const long long*)ei;
        g_src[e] = (int)p[e];
        g_dst[e] = (int)p[NEDGES + e];
    } else {
        const int* p = (const int*)ei;
        g_src[e] = p[e];
        g_dst[e] = p[NEDGES + e];
    }
}

// ---------------------------------------------------------------------------
// CSR build: zero counters, histogram by dst, 1-block scan, fill.
// ---------------------------------------------------------------------------
__global__ __launch_bounds__(256) void zero_cnt_kernel()
{
    int i = blockIdx.x * blockDim.x + threadIdx.x;
    if (i < NN) { g_cnt[i] = 0; g_cur[i] = 0; }
}

__global__ __launch_bounds__(256) void hist_kernel()
{
    int e = blockIdx.x * blockDim.x + threadIdx.x;
    if (e < NEDGES) atomicAdd(&g_cnt[g_dst[e]], 1);
}

__global__ __launch_bounds__(1024) void scan_kernel()
{
    __shared__ int part[1024];
    const int CH = 49;  // 1024*49 = 50176 >= NN
    int t = threadIdx.x;
    int lo = t * CH, hi = min(lo + CH, NN);
    int sum = 0;
    for (int i = lo; i < hi; i++) sum += g_cnt[i];
    part[t] = sum;
    __syncthreads();
    // inclusive Hillis-Steele scan
    for (int o = 1; o < 1024; o <<= 1) {
        int v = (t >= o) ? part[t - o] : 0;
        __syncthreads();
        part[t] += v;
        __syncthreads();
    }
    int run = part[t] - sum;  // exclusive prefix at chunk start
    for (int i = lo; i < hi; i++) { g_off[i] = run; run += g_cnt[i]; }
    if (t == 1023) g_off[NN] = run;
}

__global__ __launch_bounds__(256) void fill_kernel(const float* __restrict__ ew)
{
    int e = blockIdx.x * blockDim.x + threadIdx.x;
    if (e >= NEDGES) return;
    int d = g_dst[e];
    int pos = g_off[d] + atomicAdd(&g_cur[d], 1);
    g_csr[pos] = make_int2(g_src[e], __float_as_int(ew[e]));
}

// ---------------------------------------------------------------------------
// GEMM: C = op(A) @ W (+bias). 128x128 tile, 256 threads, 8x8 microtile.
// If LN: op(A) = relu((A - mu) * rsig * gamma + beta), per-row stats in g_stats.
// ---------------------------------------------------------------------------
template<bool LN>
__global__ __launch_bounds__(256) void gemm_kernel(
    const float* __restrict__ A, int lda,
    const float* __restrict__ W,
    const float* __restrict__ bias, float* __restrict__ C,
    int nrows, int K, int ldw, int ldc,
    const float* __restrict__ gamma, const float* __restrict__ beta)
{
    __shared__ float As[16][128];
    __shared__ float Bs[16][128];

    const int tid = threadIdx.x;
    const int rowblk = blockIdx.x * 128;
    const int colblk = blockIdx.y * 128;
    const int trow = (tid >> 4) * 8;
    const int tcol = (tid & 15) * 8;

    float acc[8][8];
#pragma unroll
    for (int i = 0; i < 8; i++)
#pragma unroll
        for (int j = 0; j < 8; j++) acc[i][j] = 0.f;

    for (int kt = 0; kt < K; kt += 16) {
#pragma unroll
        for (int i = 0; i < 2; i++) {
            int q = tid + i * 256;
            int r = q >> 2;
            int k4 = (q & 3) * 4;
            int grow = rowblk + r;
            float4 v = make_float4(0.f, 0.f, 0.f, 0.f);
            if (grow < nrows) {
                v = *(const float4*)(A + (size_t)grow * lda + kt + k4);
                if (LN) {
                    float2 st = g_stats[grow];  // (mu, rsig) — 4-thread broadcast
                    float4 g4 = *(const float4*)(gamma + kt + k4);
                    float4 b4 = *(const float4*)(beta + kt + k4);
                    v.x = fmaxf((v.x - st.x) * st.y * g4.x + b4.x, 0.f);
                    v.y = fmaxf((v.y - st.x) * st.y * g4.y + b4.y, 0.f);
                    v.z = fmaxf((v.z - st.x) * st.y * g4.z + b4.z, 0.f);
                    v.w = fmaxf((v.w - st.x) * st.y * g4.w + b4.w, 0.f);
                }
            }
            As[k4 + 0][r] = v.x;
            As[k4 + 1][r] = v.y;
            As[k4 + 2][r] = v.z;
            As[k4 + 3][r] = v.w;
        }
#pragma unroll
        for (int i = 0; i < 2; i++) {
            int q = tid + i * 256;
            int kk = q >> 5;
            int c4 = (q & 31) * 4;
            float4 v = *(const float4*)(W + (size_t)(kt + kk) * ldw + colblk + c4);
            *(float4*)&Bs[kk][c4] = v;
        }
        __syncthreads();

#pragma unroll
        for (int kk = 0; kk < 16; kk++) {
            float ra[8], rb[8];
#pragma unroll
            for (int i = 0; i < 8; i++) ra[i] = As[kk][trow + i];
#pragma unroll
            for (int j = 0; j < 8; j++) rb[j] = Bs[kk][tcol + j];
#pragma unroll
            for (int i = 0; i < 8; i++)
#pragma unroll
                for (int j = 0; j < 8; j++)
                    acc[i][j] = fmaf(ra[i], rb[j], acc[i][j]);
        }
        __syncthreads();
    }

#pragma unroll
    for (int i = 0; i < 8; i++) {
        int grow = rowblk + trow + i;
        if (grow >= nrows) break;
#pragma unroll
        for (int j = 0; j < 8; j += 4) {
            float4 v;
            v.x = acc[i][j + 0];
            v.y = acc[i][j + 1];
            v.z = acc[i][j + 2];
            v.w = acc[i][j + 3];
            if (bias != nullptr) {
                v.x += bias[colblk + tcol + j + 0];
                v.y += bias[colblk + tcol + j + 1];
                v.z += bias[colblk + tcol + j + 2];
                v.w += bias[colblk + tcol + j + 3];
            }
            *(float4*)(C + (size_t)grow * ldc + colblk + tcol + j) = v;
        }
    }
}

// ---------------------------------------------------------------------------
// Standalone LN stats (only after lin1): mu, rsig over h[:, colofs:colofs+128]
// ---------------------------------------------------------------------------
__global__ __launch_bounds__(256) void ln_stats_kernel(
    const float* __restrict__ h, int colofs)
{
    int row = blockIdx.x * 8 + (threadIdx.x >> 5);
    int lane = threadIdx.x & 31;
    if (row >= NN) return;
    float4 v = ((const float4*)(h + (size_t)row * HID + colofs))[lane];
    float s  = v.x + v.y + v.z + v.w;
    float sq = v.x * v.x + v.y * v.y + v.z * v.z + v.w * v.w;
#pragma unroll
    for (int o = 16; o; o >>= 1) {
        s  += __shfl_xor_sync(0xffffffffu, s, o);
        sq += __shfl_xor_sync(0xffffffffu, sq, o);
    }
    if (lane == 0) {
        float mu  = s * (1.f / 128.f);
        float var = sq * (1.f / 128.f) - mu * mu;
        g_stats[row] = make_float2(mu, rsqrtf(var + LN_EPS));
    }
}

// ---------------------------------------------------------------------------
// CSR gather: h[row, out_ofs+c] += conv_b[c] + sum_e w_e * z[src_e, c].
// One warp per destination node, float4 per lane. Epilogue writes LN stats
// of the updated 128-col slice (consumed by the NEXT block's fused GEMM).
// ---------------------------------------------------------------------------
__global__ __launch_bounds__(256) void gather_kernel(
    const float* __restrict__ z, const float* __restrict__ bias,
    float* __restrict__ h, int out_ofs)
{
    int row = blockIdx.x * 8 + (threadIdx.x >> 5);
    int lane = threadIdx.x & 31;
    if (row >= NN) return;

    float4 acc = ((const float4*)bias)[lane];
    int s = g_off[row], e = g_off[row + 1];

    int i = s;
    for (; i + 2 <= e; i += 2) {
        int2 m0 = g_csr[i];
        int2 m1 = g_csr[i + 1];
        float w0 = __int_as_float(m0.y);
        float w1 = __int_as_float(m1.y);
        float4 v0 = ((const float4*)(z + (size_t)m0.x * GC))[lane];
        float4 v1 = ((const float4*)(z + (size_t)m1.x * GC))[lane];
        acc.x = fmaf(w0, v0.x, acc.x); acc.y = fmaf(w0, v0.y, acc.y);
        acc.z = fmaf(w0, v0.z, acc.z); acc.w = fmaf(w0, v0.w, acc.w);
        acc.x = fmaf(w1, v1.x, acc.x); acc.y = fmaf(w1, v1.y, acc.y);
        acc.z = fmaf(w1, v1.z, acc.z); acc.w = fmaf(w1, v1.w, acc.w);
    }
    if (i < e) {
        int2 m = g_csr[i];
        float w = __int_as_float(m.y);
        float4 v = ((const float4*)(z + (size_t)m.x * GC))[lane];
        acc.x = fmaf(w, v.x, acc.x); acc.y = fmaf(w, v.y, acc.y);
        acc.z = fmaf(w, v.z, acc.z); acc.w = fmaf(w, v.w, acc.w);
    }

    float4* hp = (float4*)(h + (size_t)row * HID + out_ofs);
    float4 hv = hp[lane];
    hv.x += acc.x; hv.y += acc.y; hv.z += acc.z; hv.w += acc.w;
    hp[lane] = hv;

    // LN stats of updated slice
    float sm  = hv.x + hv.y + hv.z + hv.w;
    float sq  = hv.x * hv.x + hv.y * hv.y + hv.z * hv.z + hv.w * hv.w;
#pragma unroll
    for (int o = 16; o; o >>= 1) {
        sm += __shfl_xor_sync(0xffffffffu, sm, o);
        sq += __shfl_xor_sync(0xffffffffu, sq, o);
    }
    if (lane == 0) {
        float mu  = sm * (1.f / 128.f);
        float var = sq * (1.f / 128.f) - mu * mu;
        g_stats[row] = make_float2(mu, rsqrtf(var + LN_EPS));
    }
}

// ---------------------------------------------------------------------------
// lin2 with fused final LayerNorm+ReLU: out = relu(LN(h)) @ W + b.
// One warp per row.
// ---------------------------------------------------------------------------
__global__ __launch_bounds__(256) void lin2_kernel(
    const float* __restrict__ h,
    const float* __restrict__ gamma, const float* __restrict__ beta,
    const float* __restrict__ W, const float* __restrict__ b,
    float* __restrict__ out)
{
    __shared__ float ws[OUT_C * HID];  // [c][k], 40 KB
    int tid = threadIdx.x;
    for (int i = tid; i < OUT_C * HID; i += 256) {
        int c = i >> 8;
        int k = i & 255;
        ws[i] = W[k * OUT_C + c];
    }
    __syncthreads();

    int row = blockIdx.x * 8 + (tid >> 5);
    int lane = tid & 31;
    if (row >= NN) return;

    const float4* fp = (const float4*)(h + (size_t)row * HID);
    float4 a  = fp[lane];
    float4 bb = fp[lane + 32];

    float s  = a.x + a.y + a.z + a.w + bb.x + bb.y + bb.z + bb.w;
    float sq = a.x * a.x + a.y * a.y + a.z * a.z + a.w * a.w
             + bb.x * bb.x + bb.y * bb.y + bb.z * bb.z + bb.w * bb.w;
#pragma unroll
    for (int o = 16; o; o >>= 1) {
        s  += __shfl_xor_sync(0xffffffffu, s, o);
        sq += __shfl_xor_sync(0xffffffffu, sq, o);
    }
    float mu  = s * (1.f / 256.f);
    float var = sq * (1.f / 256.f) - mu * mu;
    float rs  = rsqrtf(var + LN_EPS);

    float4 g0 = ((const float4*)gamma)[lane];
    float4 g1 = ((const float4*)gamma)[lane + 32];
    float4 b0 = ((const float4*)beta)[lane];
    float4 b1 = ((const float4*)beta)[lane + 32];
    a.x  = fmaxf((a.x  - mu) * rs * g0.x + b0.x, 0.f);
    a.y  = fmaxf((a.y  - mu) * rs * g0.y + b0.y, 0.f);
    a.z  = fmaxf((a.z  - mu) * rs * g0.z + b0.z, 0.f);
    a.w  = fmaxf((a.w  - mu) * rs * g0.w + b0.w, 0.f);
    bb.x = fmaxf((bb.x - mu) * rs * g1.x + b1.x, 0.f);
    bb.y = fmaxf((bb.y - mu) * rs * g1.y + b1.y, 0.f);
    bb.z = fmaxf((bb.z - mu) * rs * g1.z + b1.z, 0.f);
    bb.w = fmaxf((bb.w - mu) * rs * g1.w + b1.w, 0.f);

    int k0 = lane * 4;
#pragma unroll 4
    for (int c = 0; c < OUT_C; c++) {
        const float* wc = ws + c * HID;
        float p = a.x * wc[k0] + a.y * wc[k0 + 1] + a.z * wc[k0 + 2] + a.w * wc[k0 + 3]
                + bb.x * wc[128 + k0] + bb.y * wc[128 + k0 + 1]
                + bb.z * wc[128 + k0 + 2] + bb.w * wc[128 + k0 + 3];
#pragma unroll
        for (int o = 16; o; o >>= 1) p += __shfl_xor_sync(0xffffffffu, p, o);
        if (lane == 0) out[(size_t)row * OUT_C + c] = p + b[c];
    }
}

// ---------------------------------------------------------------------------
extern "C" void kernel_launch(void* const* d_in, const int* in_sizes, int n_in,
                              void* d_out, int out_size)
{
    const float* x       = (const float*)d_in[0];
    const void*  ei      = d_in[1];
    const float* ew      = (const float*)d_in[2];
    const float* lin1_w  = (const float*)d_in[3];
    const float* lin1_b  = (const float*)d_in[4];
    const float* lin2_w  = (const float*)d_in[5];
    const float* lin2_b  = (const float*)d_in[6];
    const float* norm_g  = (const float*)d_in[7];
    const float* norm_b  = (const float*)d_in[8];
    const float* conv_w  = (const float*)d_in[9];
    const float* conv_b  = (const float*)d_in[10];
    const float* fnorm_g = (const float*)d_in[11];
    const float* fnorm_b = (const float*)d_in[12];
    float*       out     = (float*)d_out;

    float *h, *z;
    cudaGetSymbolAddress((void**)&h, g_h);
    cudaGetSymbolAddress((void**)&z, g_z);

    const int GEMM_BX = (NN + 127) / 128;      // 391
    const int ROW_BLKS = NN / 8;               // 6250
    const int E_BLKS = (NEDGES + 255) / 256;
    const int N_BLKS = (NN + 255) / 256;

    // Edge decode + CSR build (amortized over 8 gathers)
    detect_idx_kernel<<<1, 256>>>((const int*)ei);
    convert_idx_kernel<<<E_BLKS, 256>>>(ei);
    zero_cnt_kernel<<<N_BLKS, 256>>>();
    hist_kernel<<<E_BLKS, 256>>>();
    scan_kernel<<<1, 1024>>>();
    fill_kernel<<<E_BLKS, 256>>>(ew);

    // lin1: h = x @ lin1_w + lin1_b  [N,256]
    gemm_kernel<false><<<dim3(GEMM_BX, 2), 256>>>(
        x, IN_C, lin1_w, lin1_b, h, NN, IN_C, HID, HID, nullptr, nullptr);
    // stats for first block input (cols 128:256)
    ln_stats_kernel<<<ROW_BLKS, 256>>>(h, GC);

    for (int l = 0; l < NLAYERS; l++) {
        for (int g = 0; g < NGROUPS; g++) {
            int in_ofs  = (g == 0) ? GC : 0;
            int out_ofs = g * GC;
            int bidx = l * NGROUPS + g;

            // z = relu(LN(h[:, in_ofs:in_ofs+128])) @ conv_w
            gemm_kernel<true><<<dim3(GEMM_BX, 1), 256>>>(
                h + in_ofs, HID, conv_w + (size_t)bidx * GC * GC, nullptr, z,
                NN, GC, GC, GC,
                norm_g + (size_t)bidx * GC, norm_b + (size_t)bidx * GC);
            // h[:, out_ofs] += conv_b + scatter; writes next LN stats
            gather_kernel<<<ROW_BLKS, 256>>>(z, conv_b + (size_t)bidx * GC, h, out_ofs);
        }
    }

    lin2_kernel<<<ROW_BLKS, 256>>>(h, fnorm_g, fnorm_b, lin2_w, lin2_b, out);
}

// round 4
// speedup vs baseline: 2.8934x; 1.3748x over previous
#include <cuda_runtime.h>
#include <cuda_bf16.h>
#include <cstdint>

#define NN      50000
#define IN_C    128
#define HID     256
#define OUT_C   40
#define NLAYERS 4
#define NGROUPS 2
#define GC      128
#define NEDGES  600000
#define LN_EPS  1e-5f

// Scratch (device globals: allocation-free)
__device__ float  g_h[(size_t)NN * HID];     // node features [N,256]
__device__ float  g_z[(size_t)NN * GC];      // conv GEMM output [N,128]
__device__ float2 g_stats[NN];               // per-row (mu, rsigma) for next LN
__device__ int    g_src[NEDGES];
__device__ int    g_dst[NEDGES];
__device__ int    g_cnt[NN];
__device__ int    g_cur[NN];
__device__ int    g_off[NN + 1];
__device__ int2   g_csr[NEDGES];             // (src, bitcast weight) sorted by dst
__device__ int    g_is64;

// ---------------------------------------------------------------------------
// Edge-index dtype detection (int64 vs int32)
// ---------------------------------------------------------------------------
__global__ void detect_idx_kernel(const int* __restrict__ ei32)
{
    __shared__ int nz;
    if (threadIdx.x == 0) nz = 0;
    __syncthreads();
    int bad = 0;
    for (int i = threadIdx.x; i < 2048; i += blockDim.x)
        if (ei32[2 * i + 1] != 0) bad = 1;
    if (bad) atomicOr(&nz, 1);
    __syncthreads();
    if (threadIdx.x == 0) g_is64 = (nz == 0) ? 1 : 0;
}

__global__ __launch_bounds__(256) void convert_idx_kernel(const void* __restrict__ ei)
{
    int e = blockIdx.x * blockDim.x + threadIdx.x;
    if (e >= NEDGES) return;
    if (g_is64) {
        const long long* p = (const long long*)ei;
        g_src[e] = (int)p[e];
        g_dst[e] = (int)p[NEDGES + e];
    } else {
        const int* p = (const int*)ei;
        g_src[e] = p[e];
        g_dst[e] = p[NEDGES + e];
    }
}

// ---------------------------------------------------------------------------
// CSR build
// ---------------------------------------------------------------------------
__global__ __launch_bounds__(256) void zero_cnt_kernel()
{
    int i = blockIdx.x * blockDim.x + threadIdx.x;
    if (i < NN) { g_cnt[i] = 0; g_cur[i] = 0; }
}

__global__ __launch_bounds__(256) void hist_kernel()
{
    int e = blockIdx.x * blockDim.x + threadIdx.x;
    if (e < NEDGES) atomicAdd(&g_cnt[g_dst[e]], 1);
}

__global__ __launch_bounds__(1024) void scan_kernel()
{
    __shared__ int part[1024];
    const int CH = 49;
    int t = threadIdx.x;
    int lo = t * CH, hi = min(lo + CH, NN);
    int sum = 0;
    for (int i = lo; i < hi; i++) sum += g_cnt[i];
    part[t] = sum;
    __syncthreads();
    for (int o = 1; o < 1024; o <<= 1) {
        int v = (t >= o) ? part[t - o] : 0;
        __syncthreads();
        part[t] += v;
        __syncthreads();
    }
    int run = part[t] - sum;
    for (int i = lo; i < hi; i++) { g_off[i] = run; run += g_cnt[i]; }
    if (t == 1023) g_off[NN] = run;
}

__global__ __launch_bounds__(256) void fill_kernel(const float* __restrict__ ew)
{
    int e = blockIdx.x * blockDim.x + threadIdx.x;
    if (e >= NEDGES) return;
    int d = g_dst[e];
    int pos = g_off[d] + atomicAdd(&g_cur[d], 1);
    g_csr[pos] = make_int2(g_src[e], __float_as_int(ew[e]));
}

// ---------------------------------------------------------------------------
// tf32 tensor-core GEMM. 128x128 block tile, 8 warps (4x2), 32x64 warp tile,
// K-tile 32, mma.m16n8k8. Optional fused LN+ReLU on A rows (stats in g_stats).
// As[m][k] stride 36 and Bs[k][n] stride 136 -> conflict-free fragment LDS.
// ---------------------------------------------------------------------------
#define AS_STRIDE 36
#define BS_STRIDE 136

__device__ __forceinline__ uint32_t f2tf32(float x)
{
    uint32_t r;
    asm("cvt.rna.tf32.f32 %0, %1;" : "=r"(r) : "f"(x));
    return r;
}

__device__ __forceinline__ void mma_tf32(float* c, const uint32_t* a,
                                         uint32_t b0, uint32_t b1)
{
    asm volatile(
        "mma.sync.aligned.m16n8k8.row.col.f32.tf32.tf32.f32 "
        "{%0,%1,%2,%3}, {%4,%5,%6,%7}, {%8,%9}, {%0,%1,%2,%3};"
        : "+f"(c[0]), "+f"(c[1]), "+f"(c[2]), "+f"(c[3])
        : "r"(a[0]), "r"(a[1]), "r"(a[2]), "r"(a[3]), "r"(b0), "r"(b1));
}

template<bool LN>
__global__ __launch_bounds__(256) void gemm_tf32_kernel(
    const float* __restrict__ A, int lda,
    const float* __restrict__ W, int ldw,
    const float* __restrict__ bias, float* __restrict__ C, int ldc,
    int nrows, int K,
    const float* __restrict__ gamma, const float* __restrict__ beta)
{
    __shared__ uint32_t As[128 * AS_STRIDE];
    __shared__ uint32_t Bs[32 * BS_STRIDE];

    const int tid  = threadIdx.x;
    const int wid  = tid >> 5;
    const int lane = tid & 31;
    const int gid  = lane >> 2;   // group id 0..7
    const int tig  = lane & 3;    // thread in group 0..3
    const int wm   = (wid & 3) * 32;
    const int wn   = (wid >> 2) * 64;
    const int rowblk = blockIdx.x * 128;
    const int colblk = blockIdx.y * 128;

    float c[2][8][4];
#pragma unroll
    for (int mt = 0; mt < 2; mt++)
#pragma unroll
        for (int nt = 0; nt < 8; nt++)
#pragma unroll
            for (int r = 0; r < 4; r++) c[mt][nt][r] = 0.f;

    for (int kt = 0; kt < K; kt += 32) {
        // A tile: 128 rows x 32 k  (LN+ReLU fused on load)
#pragma unroll
        for (int i = 0; i < 4; i++) {
            int q  = tid + i * 256;       // 0..1023
            int r  = q >> 3;              // 0..127
            int c4 = (q & 7) * 4;         // 0..28
            int grow = rowblk + r;
            float4 v = make_float4(0.f, 0.f, 0.f, 0.f);
            if (grow < nrows) {
                v = *(const float4*)(A + (size_t)grow * lda + kt + c4);
                if (LN) {
                    float2 st = g_stats[grow];
                    float4 g4 = *(const float4*)(gamma + kt + c4);
                    float4 b4 = *(const float4*)(beta + kt + c4);
                    v.x = fmaxf((v.x - st.x) * st.y * g4.x + b4.x, 0.f);
                    v.y = fmaxf((v.y - st.x) * st.y * g4.y + b4.y, 0.f);
                    v.z = fmaxf((v.z - st.x) * st.y * g4.z + b4.z, 0.f);
                    v.w = fmaxf((v.w - st.x) * st.y * g4.w + b4.w, 0.f);
                }
            }
            uint4 t;
            t.x = f2tf32(v.x); t.y = f2tf32(v.y);
            t.z = f2tf32(v.z); t.w = f2tf32(v.w);
            *(uint4*)&As[r * AS_STRIDE + c4] = t;
        }
        // B tile: 32 k x 128 cols
#pragma unroll
        for (int i = 0; i < 4; i++) {
            int q  = tid + i * 256;
            int kk = q >> 5;              // 0..31
            int c4 = (q & 31) * 4;        // 0..124
            float4 v = *(const float4*)(W + (size_t)(kt + kk) * ldw + colblk + c4);
            uint4 t;
            t.x = f2tf32(v.x); t.y = f2tf32(v.y);
            t.z = f2tf32(v.z); t.w = f2tf32(v.w);
            *(uint4*)&Bs[kk * BS_STRIDE + c4] = t;
        }
        __syncthreads();

#pragma unroll
        for (int ks = 0; ks < 4; ks++) {
            int k0 = ks * 8;
            uint32_t a[2][4];
#pragma unroll
            for (int mt = 0; mt < 2; mt++) {
                int m = wm + mt * 16 + gid;
                a[mt][0] = As[m * AS_STRIDE + k0 + tig];
                a[mt][1] = As[(m + 8) * AS_STRIDE + k0 + tig];
                a[mt][2] = As[m * AS_STRIDE + k0 + tig + 4];
                a[mt][3] = As[(m + 8) * AS_STRIDE + k0 + tig + 4];
            }
#pragma unroll
            for (int nt = 0; nt < 8; nt++) {
                int n = wn + nt * 8 + gid;
                uint32_t b0 = Bs[(k0 + tig) * BS_STRIDE + n];
                uint32_t b1 = Bs[(k0 + tig + 4) * BS_STRIDE + n];
                mma_tf32(c[0][nt], a[0], b0, b1);
                mma_tf32(c[1][nt], a[1], b0, b1);
            }
        }
        __syncthreads();
    }

    // Epilogue: c0,c1 -> (row, 2tig), (row, 2tig+1); c2,c3 -> row+8
#pragma unroll
    for (int mt = 0; mt < 2; mt++) {
        int row0 = rowblk + wm + mt * 16 + gid;
        int row1 = row0 + 8;
#pragma unroll
        for (int nt = 0; nt < 8; nt++) {
            int col = colblk + wn + nt * 8 + 2 * tig;
            float bx = 0.f, by = 0.f;
            if (bias != nullptr) { bx = bias[col]; by = bias[col + 1]; }
            if (row0 < nrows) {
                float2 v = make_float2(c[mt][nt][0] + bx, c[mt][nt][1] + by);
                *(float2*)(C + (size_t)row0 * ldc + col) = v;
            }
            if (row1 < nrows) {
                float2 v = make_float2(c[mt][nt][2] + bx, c[mt][nt][3] + by);
                *(float2*)(C + (size_t)row1 * ldc + col) = v;
            }
        }
    }
}

// ---------------------------------------------------------------------------
// Standalone LN stats (only after lin1)
// ---------------------------------------------------------------------------
__global__ __launch_bounds__(256) void ln_stats_kernel(
    const float* __restrict__ h, int colofs)
{
    int row = blockIdx.x * 8 + (threadIdx.x >> 5);
    int lane = threadIdx.x & 31;
    if (row >= NN) return;
    float4 v = ((const float4*)(h + (size_t)row * HID + colofs))[lane];
    float s  = v.x + v.y + v.z + v.w;
    float sq = v.x * v.x + v.y * v.y + v.z * v.z + v.w * v.w;
#pragma unroll
    for (int o = 16; o; o >>= 1) {
        s  += __shfl_xor_sync(0xffffffffu, s, o);
        sq += __shfl_xor_sync(0xffffffffu, sq, o);
    }
    if (lane == 0) {
        float mu  = s * (1.f / 128.f);
        float var = sq * (1.f / 128.f) - mu * mu;
        g_stats[row] = make_float2(mu, rsqrtf(var + LN_EPS));
    }
}

// ---------------------------------------------------------------------------
// CSR gather + bias + in-place h update + next-LN stats
// ---------------------------------------------------------------------------
__global__ __launch_bounds__(256) void gather_kernel(
    const float* __restrict__ z, const float* __restrict__ bias,
    float* __restrict__ h, int out_ofs)
{
    int row = blockIdx.x * 8 + (threadIdx.x >> 5);
    int lane = threadIdx.x & 31;
    if (row >= NN) return;

    float4 acc = ((const float4*)bias)[lane];
    int s = g_off[row], e = g_off[row + 1];

    int i = s;
    for (; i + 2 <= e; i += 2) {
        int2 m0 = g_csr[i];
        int2 m1 = g_csr[i + 1];
        float w0 = __int_as_float(m0.y);
        float w1 = __int_as_float(m1.y);
        float4 v0 = ((const float4*)(z + (size_t)m0.x * GC))[lane];
        float4 v1 = ((const float4*)(z + (size_t)m1.x * GC))[lane];
        acc.x = fmaf(w0, v0.x, acc.x); acc.y = fmaf(w0, v0.y, acc.y);
        acc.z = fmaf(w0, v0.z, acc.z); acc.w = fmaf(w0, v0.w, acc.w);
        acc.x = fmaf(w1, v1.x, acc.x); acc.y = fmaf(w1, v1.y, acc.y);
        acc.z = fmaf(w1, v1.z, acc.z); acc.w = fmaf(w1, v1.w, acc.w);
    }
    if (i < e) {
        int2 m = g_csr[i];
        float w = __int_as_float(m.y);
        float4 v = ((const float4*)(z + (size_t)m.x * GC))[lane];
        acc.x = fmaf(w, v.x, acc.x); acc.y = fmaf(w, v.y, acc.y);
        acc.z = fmaf(w, v.z, acc.z); acc.w = fmaf(w, v.w, acc.w);
    }

    float4* hp = (float4*)(h + (size_t)row * HID + out_ofs);
    float4 hv = hp[lane];
    hv.x += acc.x; hv.y += acc.y; hv.z += acc.z; hv.w += acc.w;
    hp[lane] = hv;

    float sm = hv.x + hv.y + hv.z + hv.w;
    float sq = hv.x * hv.x + hv.y * hv.y + hv.z * hv.z + hv.w * hv.w;
#pragma unroll
    for (int o = 16; o; o >>= 1) {
        sm += __shfl_xor_sync(0xffffffffu, sm, o);
        sq += __shfl_xor_sync(0xffffffffu, sq, o);
    }
    if (lane == 0) {
        float mu  = sm * (1.f / 128.f);
        float var = sq * (1.f / 128.f) - mu * mu;
        g_stats[row] = make_float2(mu, rsqrtf(var + LN_EPS));
    }
}

// ---------------------------------------------------------------------------
// lin2 with fused final LayerNorm+ReLU
// ---------------------------------------------------------------------------
__global__ __launch_bounds__(256) void lin2_kernel(
    const float* __restrict__ h,
    const float* __restrict__ gamma, const float* __restrict__ beta,
    const float* __restrict__ W, const float* __restrict__ b,
    float* __restrict__ out)
{
    __shared__ float ws[OUT_C * HID];
    int tid = threadIdx.x;
    for (int i = tid; i < OUT_C * HID; i += 256) {
        int c = i >> 8;
        int k = i & 255;
        ws[i] = W[k * OUT_C + c];
    }
    __syncthreads();

    int row = blockIdx.x * 8 + (tid >> 5);
    int lane = tid & 31;
    if (row >= NN) return;

    const float4* fp = (const float4*)(h + (size_t)row * HID);
    float4 a  = fp[lane];
    float4 bb = fp[lane + 32];

    float s  = a.x + a.y + a.z + a.w + bb.x + bb.y + bb.z + bb.w;
    float sq = a.x * a.x + a.y * a.y + a.z * a.z + a.w * a.w
             + bb.x * bb.x + bb.y * bb.y + bb.z * bb.z + bb.w * bb.w;
#pragma unroll
    for (int o = 16; o; o >>= 1) {
        s  += __shfl_xor_sync(0xffffffffu, s, o);
        sq += __shfl_xor_sync(0xffffffffu, sq, o);
    }
    float mu  = s * (1.f / 256.f);
    float var = sq * (1.f / 256.f) - mu * mu;
    float rs  = rsqrtf(var + LN_EPS);

    float4 g0 = ((const float4*)gamma)[lane];
    float4 g1 = ((const float4*)gamma)[lane + 32];
    float4 b0 = ((const float4*)beta)[lane];
    float4 b1 = ((const float4*)beta)[lane + 32];
    a.x  = fmaxf((a.x  - mu) * rs * g0.x + b0.x, 0.f);
    a.y  = fmaxf((a.y  - mu) * rs * g0.y + b0.y, 0.f);
    a.z  = fmaxf((a.z  - mu) * rs * g0.z + b0.z, 0.f);
    a.w  = fmaxf((a.w  - mu) * rs * g0.w + b0.w, 0.f);
    bb.x = fmaxf((bb.x - mu) * rs * g1.x + b1.x, 0.f);
    bb.y = fmaxf((bb.y - mu) * rs * g1.y + b1.y, 0.f);
    bb.z = fmaxf((bb.z - mu) * rs * g1.z + b1.z, 0.f);
    bb.w = fmaxf((bb.w - mu) * rs * g1.w + b1.w, 0.f);

    int k0 = lane * 4;
#pragma unroll 4
    for (int c = 0; c < OUT_C; c++) {
        const float* wc = ws + c * HID;
        float p = a.x * wc[k0] + a.y * wc[k0 + 1] + a.z * wc[k0 + 2] + a.w * wc[k0 + 3]
                + bb.x * wc[128 + k0] + bb.y * wc[128 + k0 + 1]
                + bb.z * wc[128 + k0 + 2] + bb.w * wc[128 + k0 + 3];
#pragma unroll
        for (int o = 16; o; o >>= 1) p += __shfl_xor_sync(0xffffffffu, p, o);
        if (lane == 0) out[(size_t)row * OUT_C + c] = p + b[c];
    }
}

// ---------------------------------------------------------------------------
extern "C" void kernel_launch(void* const* d_in, const int* in_sizes, int n_in,
                              void* d_out, int out_size)
{
    const float* x       = (const float*)d_in[0];
    const void*  ei      = d_in[1];
    const float* ew      = (const float*)d_in[2];
    const float* lin1_w  = (const float*)d_in[3];
    const float* lin1_b  = (const float*)d_in[4];
    const float* lin2_w  = (const float*)d_in[5];
    const float* lin2_b  = (const float*)d_in[6];
    const float* norm_g  = (const float*)d_in[7];
    const float* norm_b  = (const float*)d_in[8];
    const float* conv_w  = (const float*)d_in[9];
    const float* conv_b  = (const float*)d_in[10];
    const float* fnorm_g = (const float*)d_in[11];
    const float* fnorm_b = (const float*)d_in[12];
    float*       out     = (float*)d_out;

    float *h, *z;
    cudaGetSymbolAddress((void**)&h, g_h);
    cudaGetSymbolAddress((void**)&z, g_z);

    const int GEMM_BX  = (NN + 127) / 128;   // 391
    const int ROW_BLKS = NN / 8;             // 6250
    const int E_BLKS   = (NEDGES + 255) / 256;
    const int N_BLKS   = (NN + 255) / 256;

    // Edge decode + CSR build
    detect_idx_kernel<<<1, 256>>>((const int*)ei);
    convert_idx_kernel<<<E_BLKS, 256>>>(ei);
    zero_cnt_kernel<<<N_BLKS, 256>>>();
    hist_kernel<<<E_BLKS, 256>>>();
    scan_kernel<<<1, 1024>>>();
    fill_kernel<<<E_BLKS, 256>>>(ew);

    // lin1: h = x @ lin1_w + lin1_b  [N,256]
    gemm_tf32_kernel<false><<<dim3(GEMM_BX, 2), 256>>>(
        x, IN_C, lin1_w, HID, lin1_b, h, HID, NN, IN_C, nullptr, nullptr);
    ln_stats_kernel<<<ROW_BLKS, 256>>>(h, GC);

    for (int l = 0; l < NLAYERS; l++) {
        for (int g = 0; g < NGROUPS; g++) {
            int in_ofs  = (g == 0) ? GC : 0;
            int out_ofs = g * GC;
            int bidx = l * NGROUPS + g;

            gemm_tf32_kernel<true><<<dim3(GEMM_BX, 1), 256>>>(
                h + in_ofs, HID, conv_w + (size_t)bidx * GC * GC, GC, nullptr,
                z, GC, NN, GC,
                norm_g + (size_t)bidx * GC, norm_b + (size_t)bidx * GC);
            gather_kernel<<<ROW_BLKS, 256>>>(z, conv_b + (size_t)bidx * GC, h, out_ofs);
        }
    }

    lin2_kernel<<<ROW_BLKS, 256>>>(h, fnorm_g, fnorm_b, lin2_w, lin2_b, out);
}

// round 5
// speedup vs baseline: 3.1274x; 1.0809x over previous
#include <cuda_runtime.h>
#include <cuda_fp16.h>
#include <cstdint>

#define NN      50000
#define IN_C    128
#define HID     256
#define OUT_C   40
#define NLAYERS 4
#define NGROUPS 2
#define GC      128
#define NEDGES  600000
#define LN_EPS  1e-5f

// Scratch (device globals: allocation-free)
__device__ float  g_h[(size_t)NN * HID];     // node features [N,256] fp32
__device__ __half g_z[(size_t)NN * GC];      // conv GEMM output [N,128] fp16
__device__ float2 g_stats[NN];               // per-row (mu, rsigma) for next LN
__device__ int    g_cnt[NN];
__device__ int    g_cur[NN];
__device__ int    g_off[NN + 1];
__device__ int2   g_csr[NEDGES];             // (src, bitcast fp32 weight) by dst
__device__ int    g_is64;

// ---------------------------------------------------------------------------
// Edge-index dtype detection (int64 vs int32): int64 LE with values < 50000
// has all odd 32-bit words zero.
// ---------------------------------------------------------------------------
__global__ void detect_idx_kernel(const int* __restrict__ ei32)
{
    __shared__ int nz;
    if (threadIdx.x == 0) nz = 0;
    __syncthreads();
    int bad = 0;
    for (int i = threadIdx.x; i < 2048; i += blockDim.x)
        if (ei32[2 * i + 1] != 0) bad = 1;
    if (bad) atomicOr(&nz, 1);
    __syncthreads();
    if (threadIdx.x == 0) g_is64 = (nz == 0) ? 1 : 0;
}

__device__ __forceinline__ int load_idx(const void* ei, int pos)
{
    if (g_is64) return (int)((const long long*)ei)[pos];
    return ((const int*)ei)[pos];
}

// ---------------------------------------------------------------------------
// CSR build
// ---------------------------------------------------------------------------
__global__ __launch_bounds__(256) void zero_cnt_kernel()
{
    int i = blockIdx.x * blockDim.x + threadIdx.x;
    if (i < NN) { g_cnt[i] = 0; g_cur[i] = 0; }
}

__global__ __launch_bounds__(256) void hist_kernel(const void* __restrict__ ei)
{
    int e = blockIdx.x * blockDim.x + threadIdx.x;
    if (e < NEDGES) atomicAdd(&g_cnt[load_idx(ei, NEDGES + e)], 1);
}

__global__ __launch_bounds__(1024) void scan_kernel()
{
    __shared__ int part[1024];
    const int CH = 49;
    int t = threadIdx.x;
    int lo = t * CH, hi = min(lo + CH, NN);
    int sum = 0;
    for (int i = lo; i < hi; i++) sum += g_cnt[i];
    part[t] = sum;
    __syncthreads();
    for (int o = 1; o < 1024; o <<= 1) {
        int v = (t >= o) ? part[t - o] : 0;
        __syncthreads();
        part[t] += v;
        __syncthreads();
    }
    int run = part[t] - sum;
    for (int i = lo; i < hi; i++) { g_off[i] = run; run += g_cnt[i]; }
    if (t == 1023) g_off[NN] = run;
}

__global__ __launch_bounds__(256) void fill_kernel(
    const void* __restrict__ ei, const float* __restrict__ ew)
{
    int e = blockIdx.x * blockDim.x + threadIdx.x;
    if (e >= NEDGES) return;
    int srcv = load_idx(ei, e);
    int d    = load_idx(ei, NEDGES + e);
    int pos = g_off[d] + atomicAdd(&g_cur[d], 1);
    g_csr[pos] = make_int2(srcv, __float_as_int(ew[e]));
}

// ---------------------------------------------------------------------------
// tf32 tensor-core GEMM. 128x128 block tile, 8 warps (4x2), 32x64 warp tile,
// K-tile 32, mma.m16n8k8. Optional fused LN+ReLU on A rows (stats in g_stats).
// HALF_OUT: emit __half output (for z). Strides chosen conflict-free.
// ---------------------------------------------------------------------------
#define AS_STRIDE 36
#define BS_STRIDE 136

__device__ __forceinline__ uint32_t f2tf32(float x)
{
    uint32_t r;
    asm("cvt.rna.tf32.f32 %0, %1;" : "=r"(r) : "f"(x));
    return r;
}

__device__ __forceinline__ void mma_tf32(float* c, const uint32_t* a,
                                         uint32_t b0, uint32_t b1)
{
    asm volatile(
        "mma.sync.aligned.m16n8k8.row.col.f32.tf32.tf32.f32 "
        "{%0,%1,%2,%3}, {%4,%5,%6,%7}, {%8,%9}, {%0,%1,%2,%3};"
        : "+f"(c[0]), "+f"(c[1]), "+f"(c[2]), "+f"(c[3])
        : "r"(a[0]), "r"(a[1]), "r"(a[2]), "r"(a[3]), "r"(b0), "r"(b1));
}

template<bool LN, bool HALF_OUT>
__global__ __launch_bounds__(256) void gemm_tf32_kernel(
    const float* __restrict__ A, int lda,
    const float* __restrict__ W, int ldw,
    const float* __restrict__ bias, void* __restrict__ Cv, int ldc,
    int nrows, int K,
    const float* __restrict__ gamma, const float* __restrict__ beta)
{
    __shared__ uint32_t As[128 * AS_STRIDE];
    __shared__ uint32_t Bs[32 * BS_STRIDE];

    const int tid  = threadIdx.x;
    const int wid  = tid >> 5;
    const int lane = tid & 31;
    const int gid  = lane >> 2;
    const int tig  = lane & 3;
    const int wm   = (wid & 3) * 32;
    const int wn   = (wid >> 2) * 64;
    const int rowblk = blockIdx.x * 128;
    const int colblk = blockIdx.y * 128;

    float c[2][8][4];
#pragma unroll
    for (int mt = 0; mt < 2; mt++)
#pragma unroll
        for (int nt = 0; nt < 8; nt++)
#pragma unroll
            for (int r = 0; r < 4; r++) c[mt][nt][r] = 0.f;

    for (int kt = 0; kt < K; kt += 32) {
        // A tile (LN+ReLU fused)
#pragma unroll
        for (int i = 0; i < 4; i++) {
            int q  = tid + i * 256;
            int r  = q >> 3;
            int c4 = (q & 7) * 4;
            int grow = rowblk + r;
            float4 v = make_float4(0.f, 0.f, 0.f, 0.f);
            if (grow < nrows) {
                v = *(const float4*)(A + (size_t)grow * lda + kt + c4);
                if (LN) {
                    float2 st = g_stats[grow];
                    float4 g4 = *(const float4*)(gamma + kt + c4);
                    float4 b4 = *(const float4*)(beta + kt + c4);
                    v.x = fmaxf((v.x - st.x) * st.y * g4.x + b4.x, 0.f);
                    v.y = fmaxf((v.y - st.x) * st.y * g4.y + b4.y, 0.f);
                    v.z = fmaxf((v.z - st.x) * st.y * g4.z + b4.z, 0.f);
                    v.w = fmaxf((v.w - st.x) * st.y * g4.w + b4.w, 0.f);
                }
            }
            uint4 t;
            t.x = f2tf32(v.x); t.y = f2tf32(v.y);
            t.z = f2tf32(v.z); t.w = f2tf32(v.w);
            *(uint4*)&As[r * AS_STRIDE + c4] = t;
        }
        // B tile
#pragma unroll
        for (int i = 0; i < 4; i++) {
            int q  = tid + i * 256;
            int kk = q >> 5;
            int c4 = (q & 31) * 4;
            float4 v = *(const float4*)(W + (size_t)(kt + kk) * ldw + colblk + c4);
            uint4 t;
            t.x = f2tf32(v.x); t.y = f2tf32(v.y);
            t.z = f2tf32(v.z); t.w = f2tf32(v.w);
            *(uint4*)&Bs[kk * BS_STRIDE + c4] = t;
        }
        __syncthreads();

#pragma unroll
        for (int ks = 0; ks < 4; ks++) {
            int k0 = ks * 8;
            uint32_t a[2][4];
#pragma unroll
            for (int mt = 0; mt < 2; mt++) {
                int m = wm + mt * 16 + gid;
                a[mt][0] = As[m * AS_STRIDE + k0 + tig];
                a[mt][1] = As[(m + 8) * AS_STRIDE + k0 + tig];
                a[mt][2] = As[m * AS_STRIDE + k0 + tig + 4];
                a[mt][3] = As[(m + 8) * AS_STRIDE + k0 + tig + 4];
            }
#pragma unroll
            for (int nt = 0; nt < 8; nt++) {
                int n = wn + nt * 8 + gid;
                uint32_t b0 = Bs[(k0 + tig) * BS_STRIDE + n];
                uint32_t b1 = Bs[(k0 + tig + 4) * BS_STRIDE + n];
                mma_tf32(c[0][nt], a[0], b0, b1);
                mma_tf32(c[1][nt], a[1], b0, b1);
            }
        }
        __syncthreads();
    }

#pragma unroll
    for (int mt = 0; mt < 2; mt++) {
        int row0 = rowblk + wm + mt * 16 + gid;
        int row1 = row0 + 8;
#pragma unroll
        for (int nt = 0; nt < 8; nt++) {
            int col = colblk + wn + nt * 8 + 2 * tig;
            float bx = 0.f, by = 0.f;
            if (bias != nullptr) { bx = bias[col]; by = bias[col + 1]; }
            if (HALF_OUT) {
                __half* C = (__half*)Cv;
                if (row0 < nrows)
                    *(__half2*)(C + (size_t)row0 * ldc + col) =
                        __floats2half2_rn(c[mt][nt][0] + bx, c[mt][nt][1] + by);
                if (row1 < nrows)
                    *(__half2*)(C + (size_t)row1 * ldc + col) =
                        __floats2half2_rn(c[mt][nt][2] + bx, c[mt][nt][3] + by);
            } else {
                float* C = (float*)Cv;
                if (row0 < nrows)
                    *(float2*)(C + (size_t)row0 * ldc + col) =
                        make_float2(c[mt][nt][0] + bx, c[mt][nt][1] + by);
                if (row1 < nrows)
                    *(float2*)(C + (size_t)row1 * ldc + col) =
                        make_float2(c[mt][nt][2] + bx, c[mt][nt][3] + by);
            }
        }
    }
}

// ---------------------------------------------------------------------------
// Standalone LN stats (only after lin1)
// ---------------------------------------------------------------------------
__global__ __launch_bounds__(256) void ln_stats_kernel(
    const float* __restrict__ h, int colofs)
{
    int row = blockIdx.x * 8 + (threadIdx.x >> 5);
    int lane = threadIdx.x & 31;
    if (row >= NN) return;
    float4 v = ((const float4*)(h + (size_t)row * HID + colofs))[lane];
    float s  = v.x + v.y + v.z + v.w;
    float sq = v.x * v.x + v.y * v.y + v.z * v.z + v.w * v.w;
#pragma unroll
    for (int o = 16; o; o >>= 1) {
        s  += __shfl_xor_sync(0xffffffffu, s, o);
        sq += __shfl_xor_sync(0xffffffffu, sq, o);
    }
    if (lane == 0) {
        float mu  = s * (1.f / 128.f);
        float var = sq * (1.f / 128.f) - mu * mu;
        g_stats[row] = make_float2(mu, rsqrtf(var + LN_EPS));
    }
}

// ---------------------------------------------------------------------------
// CSR gather (fp16 z) + bias + in-place h update + next-LN stats.
// One warp per dst row; lane covers 4 channels = one 8B load per edge.
// ---------------------------------------------------------------------------
__device__ __forceinline__ void acc_edge(float4& acc, const __half* z,
                                         int2 m, int lane)
{
    float w = __int_as_float(m.y);
    uint2 u = *(const uint2*)(z + (size_t)m.x * GC + lane * 4);
    float2 lo = __half22float2(*(const __half2*)&u.x);
    float2 hi = __half22float2(*(const __half2*)&u.y);
    acc.x = fmaf(w, lo.x, acc.x); acc.y = fmaf(w, lo.y, acc.y);
    acc.z = fmaf(w, hi.x, acc.z); acc.w = fmaf(w, hi.y, acc.w);
}

__global__ __launch_bounds__(256) void gather_kernel(
    const __half* __restrict__ z, const float* __restrict__ bias,
    float* __restrict__ h, int out_ofs)
{
    int row = blockIdx.x * 8 + (threadIdx.x >> 5);
    int lane = threadIdx.x & 31;
    if (row >= NN) return;

    float4 acc = ((const float4*)bias)[lane];
    int s = g_off[row], e = g_off[row + 1];

    int i = s;
    for (; i + 4 <= e; i += 4) {
        int2 m0 = g_csr[i];
        int2 m1 = g_csr[i + 1];
        int2 m2 = g_csr[i + 2];
        int2 m3 = g_csr[i + 3];
        acc_edge(acc, z, m0, lane);
        acc_edge(acc, z, m1, lane);
        acc_edge(acc, z, m2, lane);
        acc_edge(acc, z, m3, lane);
    }
    for (; i < e; i++)
        acc_edge(acc, z, g_csr[i], lane);

    float4* hp = (float4*)(h + (size_t)row * HID + out_ofs);
    float4 hv = hp[lane];
    hv.x += acc.x; hv.y += acc.y; hv.z += acc.z; hv.w += acc.w;
    hp[lane] = hv;

    float sm = hv.x + hv.y + hv.z + hv.w;
    float sq = hv.x * hv.x + hv.y * hv.y + hv.z * hv.z + hv.w * hv.w;
#pragma unroll
    for (int o = 16; o; o >>= 1) {
        sm += __shfl_xor_sync(0xffffffffu, sm, o);
        sq += __shfl_xor_sync(0xffffffffu, sq, o);
    }
    if (lane == 0) {
        float mu  = sm * (1.f / 128.f);
        float var = sq * (1.f / 128.f) - mu * mu;
        g_stats[row] = make_float2(mu, rsqrtf(var + LN_EPS));
    }
}

// ---------------------------------------------------------------------------
// lin2 with fused final LayerNorm+ReLU
// ---------------------------------------------------------------------------
__global__ __launch_bounds__(256) void lin2_kernel(
    const float* __restrict__ h,
    const float* __restrict__ gamma, const float* __restrict__ beta,
    const float* __restrict__ W, const float* __restrict__ b,
    float* __restrict__ out)
{
    __shared__ float ws[OUT_C * HID];
    int tid = threadIdx.x;
    for (int i = tid; i < OUT_C * HID; i += 256) {
        int c = i >> 8;
        int k = i & 255;
        ws[i] = W[k * OUT_C + c];
    }
    __syncthreads();

    int row = blockIdx.x * 8 + (tid >> 5);
    int lane = tid & 31;
    if (row >= NN) return;

    const float4* fp = (const float4*)(h + (size_t)row * HID);
    float4 a  = fp[lane];
    float4 bb = fp[lane + 32];

    float s  = a.x + a.y + a.z + a.w + bb.x + bb.y + bb.z + bb.w;
    float sq = a.x * a.x + a.y * a.y + a.z * a.z + a.w * a.w
             + bb.x * bb.x + bb.y * bb.y + bb.z * bb.z + bb.w * bb.w;
#pragma unroll
    for (int o = 16; o; o >>= 1) {
        s  += __shfl_xor_sync(0xffffffffu, s, o);
        sq += __shfl_xor_sync(0xffffffffu, sq, o);
    }
    float mu  = s * (1.f / 256.f);
    float var = sq * (1.f / 256.f) - mu * mu;
    float rs  = rsqrtf(var + LN_EPS);

    float4 g0 = ((const float4*)gamma)[lane];
    float4 g1 = ((const float4*)gamma)[lane + 32];
    float4 b0 = ((const float4*)beta)[lane];
    float4 b1 = ((const float4*)beta)[lane + 32];
    a.x  = fmaxf((a.x  - mu) * rs * g0.x + b0.x, 0.f);
    a.y  = fmaxf((a.y  - mu) * rs * g0.y + b0.y, 0.f);
    a.z  = fmaxf((a.z  - mu) * rs * g0.z + b0.z, 0.f);
    a.w  = fmaxf((a.w  - mu) * rs * g0.w + b0.w, 0.f);
    bb.x = fmaxf((bb.x - mu) * rs * g1.x + b1.x, 0.f);
    bb.y = fmaxf((bb.y - mu) * rs * g1.y + b1.y, 0.f);
    bb.z = fmaxf((bb.z - mu) * rs * g1.z + b1.z, 0.f);
    bb.w = fmaxf((bb.w - mu) * rs * g1.w + b1.w, 0.f);

    int k0 = lane * 4;
#pragma unroll 4
    for (int c = 0; c < OUT_C; c++) {
        const float* wc = ws + c * HID;
        float p = a.x * wc[k0] + a.y * wc[k0 + 1] + a.z * wc[k0 + 2] + a.w * wc[k0 + 3]
                + bb.x * wc[128 + k0] + bb.y * wc[128 + k0 + 1]
                + bb.z * wc[128 + k0 + 2] + bb.w * wc[128 + k0 + 3];
#pragma unroll
        for (int o = 16; o; o >>= 1) p += __shfl_xor_sync(0xffffffffu, p, o);
        if (lane == 0) out[(size_t)row * OUT_C + c] = p + b[c];
    }
}

// ---------------------------------------------------------------------------
extern "C" void kernel_launch(void* const* d_in, const int* in_sizes, int n_in,
                              void* d_out, int out_size)
{
    const float* x       = (const float*)d_in[0];
    const void*  ei      = d_in[1];
    const float* ew      = (const float*)d_in[2];
    const float* lin1_w  = (const float*)d_in[3];
    const float* lin1_b  = (const float*)d_in[4];
    const float* lin2_w  = (const float*)d_in[5];
    const float* lin2_b  = (const float*)d_in[6];
    const float* norm_g  = (const float*)d_in[7];
    const float* norm_b  = (const float*)d_in[8];
    const float* conv_w  = (const float*)d_in[9];
    const float* conv_b  = (const float*)d_in[10];
    const float* fnorm_g = (const float*)d_in[11];
    const float* fnorm_b = (const float*)d_in[12];
    float*       out     = (float*)d_out;

    float  *h;
    __half *z;
    cudaGetSymbolAddress((void**)&h, g_h);
    cudaGetSymbolAddress((void**)&z, g_z);

    const int GEMM_BX  = (NN + 127) / 128;   // 391
    const int ROW_BLKS = NN / 8;             // 6250
    const int E_BLKS   = (NEDGES + 255) / 256;
    const int N_BLKS   = (NN + 255) / 256;

    // Edge decode + CSR build
    detect_idx_kernel<<<1, 256>>>((const int*)ei);
    zero_cnt_kernel<<<N_BLKS, 256>>>();
    hist_kernel<<<E_BLKS, 256>>>(ei);
    scan_kernel<<<1, 1024>>>();
    fill_kernel<<<E_BLKS, 256>>>(ei, ew);

    // lin1: h = x @ lin1_w + lin1_b  [N,256] fp32 out
    gemm_tf32_kernel<false, false><<<dim3(GEMM_BX, 2), 256>>>(
        x, IN_C, lin1_w, HID, lin1_b, h, HID, NN, IN_C, nullptr, nullptr);
    ln_stats_kernel<<<ROW_BLKS, 256>>>(h, GC);

    for (int l = 0; l < NLAYERS; l++) {
        for (int g = 0; g < NGROUPS; g++) {
            int in_ofs  = (g == 0) ? GC : 0;
            int out_ofs = g * GC;
            int bidx = l * NGROUPS + g;

            // z(fp16) = relu(LN(h[:, in_ofs:+128])) @ conv_w
            gemm_tf32_kernel<true, true><<<dim3(GEMM_BX, 1), 256>>>(
                h + in_ofs, HID, conv_w + (size_t)bidx * GC * GC, GC, nullptr,
                z, GC, NN, GC,
                norm_g + (size_t)bidx * GC, norm_b + (size_t)bidx * GC);
            // h[:, out_ofs] += conv_b + gather(w * z[src]); writes next stats
            gather_kernel<<<ROW_BLKS, 256>>>(z, conv_b + (size_t)bidx * GC, h, out_ofs);
        }
    }

    lin2_kernel<<<ROW_BLKS, 256>>>(h, fnorm_g, fnorm_b, lin2_w, lin2_b, out);
}

// round 6
// speedup vs baseline: 3.1360x; 1.0028x over previous
#include <cuda_runtime.h>
#include <cuda_fp16.h>
#include <cstdint>

#define NN      50000
#define IN_C    128
#define HID     256
#define OUT_C   40
#define NLAYERS 4
#define NGROUPS 2
#define GC      128
#define NEDGES  600000
#define LN_EPS  1e-5f
#define SCAN_BLKS 196   // 196*256 = 50176 >= NN

// Scratch (device globals: allocation-free)
__device__ float  g_h[(size_t)NN * HID];     // node features [N,256] fp32
__device__ __half g_z[(size_t)NN * GC];      // conv GEMM output [N,128] fp16
__device__ float2 g_stats[NN];               // per-row (mu, rsigma) for next LN
__device__ int    g_cnt[NN];
__device__ int    g_cur[NN];
__device__ int    g_off[NN + 1];
__device__ int    g_part[SCAN_BLKS];
__device__ int2   g_csr[NEDGES];             // (src, bitcast fp32 weight) by dst
__device__ int    g_is64;

// ---------------------------------------------------------------------------
// Edge-index dtype detection (int64 vs int32)
// ---------------------------------------------------------------------------
__global__ void detect_idx_kernel(const int* __restrict__ ei32)
{
    __shared__ int nz;
    if (threadIdx.x == 0) nz = 0;
    __syncthreads();
    int bad = 0;
    for (int i = threadIdx.x; i < 2048; i += blockDim.x)
        if (ei32[2 * i + 1] != 0) bad = 1;
    if (bad) atomicOr(&nz, 1);
    __syncthreads();
    if (threadIdx.x == 0) g_is64 = (nz == 0) ? 1 : 0;
}

__device__ __forceinline__ int load_idx(const void* ei, int pos)
{
    if (g_is64) return (int)((const long long*)ei)[pos];
    return ((const int*)ei)[pos];
}

// ---------------------------------------------------------------------------
// CSR build: zero, hist, 3-phase parallel scan, fill
// ---------------------------------------------------------------------------
__global__ __launch_bounds__(256) void zero_cnt_kernel()
{
    int i = blockIdx.x * blockDim.x + threadIdx.x;
    if (i < NN) { g_cnt[i] = 0; g_cur[i] = 0; }
}

__global__ __launch_bounds__(256) void hist_kernel(const void* __restrict__ ei)
{
    int e = blockIdx.x * blockDim.x + threadIdx.x;
    if (e < NEDGES) atomicAdd(&g_cnt[load_idx(ei, NEDGES + e)], 1);
}

__global__ __launch_bounds__(256) void scan_partial_kernel()
{
    __shared__ int sm[256];
    int i = blockIdx.x * 256 + threadIdx.x;
    int v = (i < NN) ? g_cnt[i] : 0;
    sm[threadIdx.x] = v;
    __syncthreads();
#pragma unroll
    for (int o = 128; o; o >>= 1) {
        if (threadIdx.x < o) sm[threadIdx.x] += sm[threadIdx.x + o];
        __syncthreads();
    }
    if (threadIdx.x == 0) g_part[blockIdx.x] = sm[0];
}

__global__ __launch_bounds__(256) void scan_blocks_kernel()
{
    __shared__ int sm[256];
    int t = threadIdx.x;
    int v = (t < SCAN_BLKS) ? g_part[t] : 0;
    sm[t] = v;
    __syncthreads();
#pragma unroll
    for (int o = 1; o < 256; o <<= 1) {
        int u = (t >= o) ? sm[t - o] : 0;
        __syncthreads();
        sm[t] += u;
        __syncthreads();
    }
    if (t < SCAN_BLKS) g_part[t] = sm[t] - v;  // exclusive
}

__global__ __launch_bounds__(256) void scan_final_kernel()
{
    __shared__ int sm[256];
    int t = threadIdx.x;
    int i = blockIdx.x * 256 + t;
    int v = (i < NN) ? g_cnt[i] : 0;
    sm[t] = v;
    __syncthreads();
#pragma unroll
    for (int o = 1; o < 256; o <<= 1) {
        int u = (t >= o) ? sm[t - o] : 0;
        __syncthreads();
        sm[t] += u;
        __syncthreads();
    }
    if (i <= NN) g_off[i] = g_part[blockIdx.x] + sm[t] - v;
}

__global__ __launch_bounds__(256) void fill_kernel(
    const void* __restrict__ ei, const float* __restrict__ ew)
{
    int e = blockIdx.x * blockDim.x + threadIdx.x;
    if (e >= NEDGES) return;
    int srcv = load_idx(ei, e);
    int d    = load_idx(ei, NEDGES + e);
    int pos = g_off[d] + atomicAdd(&g_cur[d], 1);
    g_csr[pos] = make_int2(srcv, __float_as_int(ew[e]));
}

// ---------------------------------------------------------------------------
// tf32 tensor-core GEMM, K fixed at 128. 128x128 block tile, 8 warps (4x2),
// 32x64 warp tile, K-tile 32, mma.m16n8k8, register-staged prefetch pipeline.
// Optional fused LN+ReLU on A (per-row stats in g_stats). HALF_OUT for z.
// ---------------------------------------------------------------------------
#define AS_STRIDE 36
#define BS_STRIDE 136

__device__ __forceinline__ uint32_t f2tf32(float x)
{
    uint32_t r;
    asm("cvt.rna.tf32.f32 %0, %1;" : "=r"(r) : "f"(x));
    return r;
}

__device__ __forceinline__ void mma_tf32(float* c, const uint32_t* a,
                                         uint32_t b0, uint32_t b1)
{
    asm volatile(
        "mma.sync.aligned.m16n8k8.row.col.f32.tf32.tf32.f32 "
        "{%0,%1,%2,%3}, {%4,%5,%6,%7}, {%8,%9}, {%0,%1,%2,%3};"
        : "+f"(c[0]), "+f"(c[1]), "+f"(c[2]), "+f"(c[3])
        : "r"(a[0]), "r"(a[1]), "r"(a[2]), "r"(a[3]), "r"(b0), "r"(b1));
}

template<bool LN, bool HALF_OUT>
__global__ __launch_bounds__(256) void gemm_tf32_kernel(
    const float* __restrict__ A, int lda,
    const float* __restrict__ W, int ldw,
    const float* __restrict__ bias, void* __restrict__ Cv, int ldc,
    int nrows,
    const float* __restrict__ gamma, const float* __restrict__ beta)
{
    __shared__ uint32_t As[128 * AS_STRIDE];
    __shared__ uint32_t Bs[32 * BS_STRIDE];

    const int tid  = threadIdx.x;
    const int wid  = tid >> 5;
    const int lane = tid & 31;
    const int gid  = lane >> 2;
    const int tig  = lane & 3;
    const int wm   = (wid & 3) * 32;
    const int wn   = (wid >> 2) * 64;
    const int rowblk = blockIdx.x * 128;
    const int colblk = blockIdx.y * 128;

    // Per-thread staging coordinates (A: 4 chunks, B: 4 chunks)
    const int ar  = tid >> 1;                 // A rows handled: ar, with c4a in {0,16}+...
    // A: q = tid + i*256 -> r = q>>3, c4 = (q&7)*4
    // B: q = tid + i*256 -> kk = q>>5, c4 = (q&31)*4

    float c[2][8][4];
#pragma unroll
    for (int mt = 0; mt < 2; mt++)
#pragma unroll
        for (int nt = 0; nt < 8; nt++)
#pragma unroll
            for (int r = 0; r < 4; r++) c[mt][nt][r] = 0.f;

    (void)ar;

    // ---- staged load of one K-tile into registers ----
    auto load_tile = [&](int kt, uint4* sa, uint4* sb) {
#pragma unroll
        for (int i = 0; i < 4; i++) {
            int q  = tid + i * 256;
            int r  = q >> 3;
            int c4 = (q & 7) * 4;
            int grow = rowblk + r;
            float4 v = make_float4(0.f, 0.f, 0.f, 0.f);
            if (grow < nrows) {
                v = *(const float4*)(A + (size_t)grow * lda + kt + c4);
                if (LN) {
                    float2 st = g_stats[grow];
                    float4 g4 = *(const float4*)(gamma + kt + c4);
                    float4 b4 = *(const float4*)(beta + kt + c4);
                    v.x = fmaxf((v.x - st.x) * st.y * g4.x + b4.x, 0.f);
                    v.y = fmaxf((v.y - st.x) * st.y * g4.y + b4.y, 0.f);
                    v.z = fmaxf((v.z - st.x) * st.y * g4.z + b4.z, 0.f);
                    v.w = fmaxf((v.w - st.x) * st.y * g4.w + b4.w, 0.f);
                }
            }
            sa[i].x = f2tf32(v.x); sa[i].y = f2tf32(v.y);
            sa[i].z = f2tf32(v.z); sa[i].w = f2tf32(v.w);
        }
#pragma unroll
        for (int i = 0; i < 4; i++) {
            int q  = tid + i * 256;
            int kk = q >> 5;
            int c4 = (q & 31) * 4;
            float4 v = *(const float4*)(W + (size_t)(kt + kk) * ldw + colblk + c4);
            sb[i].x = f2tf32(v.x); sb[i].y = f2tf32(v.y);
            sb[i].z = f2tf32(v.z); sb[i].w = f2tf32(v.w);
        }
    };

    auto store_tile = [&](const uint4* sa, const uint4* sb) {
#pragma unroll
        for (int i = 0; i < 4; i++) {
            int q  = tid + i * 256;
            int r  = q >> 3;
            int c4 = (q & 7) * 4;
            *(uint4*)&As[r * AS_STRIDE + c4] = sa[i];
        }
#pragma unroll
        for (int i = 0; i < 4; i++) {
            int q  = tid + i * 256;
            int kk = q >> 5;
            int c4 = (q & 31) * 4;
            *(uint4*)&Bs[kk * BS_STRIDE + c4] = sb[i];
        }
    };

    auto compute_tile = [&]() {
#pragma unroll
        for (int ks = 0; ks < 4; ks++) {
            int k0 = ks * 8;
            uint32_t a[2][4];
#pragma unroll
            for (int mt = 0; mt < 2; mt++) {
                int m = wm + mt * 16 + gid;
                a[mt][0] = As[m * AS_STRIDE + k0 + tig];
                a[mt][1] = As[(m + 8) * AS_STRIDE + k0 + tig];
                a[mt][2] = As[m * AS_STRIDE + k0 + tig + 4];
                a[mt][3] = As[(m + 8) * AS_STRIDE + k0 + tig + 4];
            }
#pragma unroll
            for (int nt = 0; nt < 8; nt++) {
                int n = wn + nt * 8 + gid;
                uint32_t b0 = Bs[(k0 + tig) * BS_STRIDE + n];
                uint32_t b1 = Bs[(k0 + tig + 4) * BS_STRIDE + n];
                mma_tf32(c[0][nt], a[0], b0, b1);
                mma_tf32(c[1][nt], a[1], b0, b1);
            }
        }
    };

    uint4 sa[4], sb[4];
    load_tile(0, sa, sb);
#pragma unroll
    for (int t = 0; t < 4; t++) {
        store_tile(sa, sb);
        __syncthreads();
        uint4 na[4], nb[4];
        if (t < 3) load_tile((t + 1) * 32, na, nb);   // prefetch overlaps mma
        compute_tile();
        __syncthreads();
        if (t < 3) {
#pragma unroll
            for (int i = 0; i < 4; i++) { sa[i] = na[i]; sb[i] = nb[i]; }
        }
    }

#pragma unroll
    for (int mt = 0; mt < 2; mt++) {
        int row0 = rowblk + wm + mt * 16 + gid;
        int row1 = row0 + 8;
#pragma unroll
        for (int nt = 0; nt < 8; nt++) {
            int col = colblk + wn + nt * 8 + 2 * tig;
            float bx = 0.f, by = 0.f;
            if (bias != nullptr) { bx = bias[col]; by = bias[col + 1]; }
            if (HALF_OUT) {
                __half* C = (__half*)Cv;
                if (row0 < nrows)
                    *(__half2*)(C + (size_t)row0 * ldc + col) =
                        __floats2half2_rn(c[mt][nt][0] + bx, c[mt][nt][1] + by);
                if (row1 < nrows)
                    *(__half2*)(C + (size_t)row1 * ldc + col) =
                        __floats2half2_rn(c[mt][nt][2] + bx, c[mt][nt][3] + by);
            } else {
                float* C = (float*)Cv;
                if (row0 < nrows)
                    *(float2*)(C + (size_t)row0 * ldc + col) =
                        make_float2(c[mt][nt][0] + bx, c[mt][nt][1] + by);
                if (row1 < nrows)
                    *(float2*)(C + (size_t)row1 * ldc + col) =
                        make_float2(c[mt][nt][2] + bx, c[mt][nt][3] + by);
            }
        }
    }
}

// ---------------------------------------------------------------------------
// Standalone LN stats (only after lin1)
// ---------------------------------------------------------------------------
__global__ __launch_bounds__(256) void ln_stats_kernel(
    const float* __restrict__ h, int colofs)
{
    int row = blockIdx.x * 8 + (threadIdx.x >> 5);
    int lane = threadIdx.x & 31;
    if (row >= NN) return;
    float4 v = ((const float4*)(h + (size_t)row * HID + colofs))[lane];
    float s  = v.x + v.y + v.z + v.w;
    float sq = v.x * v.x + v.y * v.y + v.z * v.z + v.w * v.w;
#pragma unroll
    for (int o = 16; o; o >>= 1) {
        s  += __shfl_xor_sync(0xffffffffu, s, o);
        sq += __shfl_xor_sync(0xffffffffu, sq, o);
    }
    if (lane == 0) {
        float mu  = s * (1.f / 128.f);
        float var = sq * (1.f / 128.f) - mu * mu;
        g_stats[row] = make_float2(mu, rsqrtf(var + LN_EPS));
    }
}

// ---------------------------------------------------------------------------
// CSR gather (fp16 z) + bias + in-place h update + next-LN stats
// ---------------------------------------------------------------------------
__device__ __forceinline__ void acc_edge(float4& acc, const __half* z,
                                         int2 m, int lane)
{
    float w = __int_as_float(m.y);
    uint2 u = *(const uint2*)(z + (size_t)m.x * GC + lane * 4);
    float2 lo = __half22float2(*(const __half2*)&u.x);
    float2 hi = __half22float2(*(const __half2*)&u.y);
    acc.x = fmaf(w, lo.x, acc.x); acc.y = fmaf(w, lo.y, acc.y);
    acc.z = fmaf(w, hi.x, acc.z); acc.w = fmaf(w, hi.y, acc.w);
}

__global__ __launch_bounds__(256) void gather_kernel(
    const __half* __restrict__ z, const float* __restrict__ bias,
    float* __restrict__ h, int out_ofs)
{
    int row = blockIdx.x * 8 + (threadIdx.x >> 5);
    int lane = threadIdx.x & 31;
    if (row >= NN) return;

    float4 acc = ((const float4*)bias)[lane];
    int s = g_off[row], e = g_off[row + 1];

    int i = s;
    for (; i + 4 <= e; i += 4) {
        int2 m0 = g_csr[i];
        int2 m1 = g_csr[i + 1];
        int2 m2 = g_csr[i + 2];
        int2 m3 = g_csr[i + 3];
        acc_edge(acc, z, m0, lane);
        acc_edge(acc, z, m1, lane);
        acc_edge(acc, z, m2, lane);
        acc_edge(acc, z, m3, lane);
    }
    for (; i < e; i++)
        acc_edge(acc, z, g_csr[i], lane);

    float4* hp = (float4*)(h + (size_t)row * HID + out_ofs);
    float4 hv = hp[lane];
    hv.x += acc.x; hv.y += acc.y; hv.z += acc.z; hv.w += acc.w;
    hp[lane] = hv;

    float sm = hv.x + hv.y + hv.z + hv.w;
    float sq = hv.x * hv.x + hv.y * hv.y + hv.z * hv.z + hv.w * hv.w;
#pragma unroll
    for (int o = 16; o; o >>= 1) {
        sm += __shfl_xor_sync(0xffffffffu, sm, o);
        sq += __shfl_xor_sync(0xffffffffu, sq, o);
    }
    if (lane == 0) {
        float mu  = sm * (1.f / 128.f);
        float var = sq * (1.f / 128.f) - mu * mu;
        g_stats[row] = make_float2(mu, rsqrtf(var + LN_EPS));
    }
}

// ---------------------------------------------------------------------------
// lin2 with fused final LayerNorm+ReLU
// ---------------------------------------------------------------------------
__global__ __launch_bounds__(256) void lin2_kernel(
    const float* __restrict__ h,
    const float* __restrict__ gamma, const float* __restrict__ beta,
    const float* __restrict__ W, const float* __restrict__ b,
    float* __restrict__ out)
{
    __shared__ float ws[OUT_C * HID];
    int tid = threadIdx.x;
    for (int i = tid; i < OUT_C * HID; i += 256) {
        int c = i >> 8;
        int k = i & 255;
        ws[i] = W[k * OUT_C + c];
    }
    __syncthreads();

    int row = blockIdx.x * 8 + (tid >> 5);
    int lane = tid & 31;
    if (row >= NN) return;

    const float4* fp = (const float4*)(h + (size_t)row * HID);
    float4 a  = fp[lane];
    float4 bb = fp[lane + 32];

    float s  = a.x + a.y + a.z + a.w + bb.x + bb.y + bb.z + bb.w;
    float sq = a.x * a.x + a.y * a.y + a.z * a.z + a.w * a.w
             + bb.x * bb.x + bb.y * bb.y + bb.z * bb.z + bb.w * bb.w;
#pragma unroll
    for (int o = 16; o; o >>= 1) {
        s  += __shfl_xor_sync(0xffffffffu, s, o);
        sq += __shfl_xor_sync(0xffffffffu, sq, o);
    }
    float mu  = s * (1.f / 256.f);
    float var = sq * (1.f / 256.f) - mu * mu;
    float rs  = rsqrtf(var + LN_EPS);

    float4 g0 = ((const float4*)gamma)[lane];
    float4 g1 = ((const float4*)gamma)[lane + 32];
    float4 b0 = ((const float4*)beta)[lane];
    float4 b1 = ((const float4*)beta)[lane + 32];
    a.x  = fmaxf((a.x  - mu) * rs * g0.x + b0.x, 0.f);
    a.y  = fmaxf((a.y  - mu) * rs * g0.y + b0.y, 0.f);
    a.z  = fmaxf((a.z  - mu) * rs * g0.z + b0.z, 0.f);
    a.w  = fmaxf((a.w  - mu) * rs * g0.w + b0.w, 0.f);
    bb.x = fmaxf((bb.x - mu) * rs * g1.x + b1.x, 0.f);
    bb.y = fmaxf((bb.y - mu) * rs * g1.y + b1.y, 0.f);
    bb.z = fmaxf((bb.z - mu) * rs * g1.z + b1.z, 0.f);
    bb.w = fmaxf((bb.w - mu) * rs * g1.w + b1.w, 0.f);

    int k0 = lane * 4;
#pragma unroll 4
    for (int c = 0; c < OUT_C; c++) {
        const float* wc = ws + c * HID;
        float p = a.x * wc[k0] + a.y * wc[k0 + 1] + a.z * wc[k0 + 2] + a.w * wc[k0 + 3]
                + bb.x * wc[128 + k0] + bb.y * wc[128 + k0 + 1]
                + bb.z * wc[128 + k0 + 2] + bb.w * wc[128 + k0 + 3];
#pragma unroll
        for (int o = 16; o; o >>= 1) p += __shfl_xor_sync(0xffffffffu, p, o);
        if (lane == 0) out[(size_t)row * OUT_C + c] = p + b[c];
    }
}

// ---------------------------------------------------------------------------
extern "C" void kernel_launch(void* const* d_in, const int* in_sizes, int n_in,
                              void* d_out, int out_size)
{
    const float* x       = (const float*)d_in[0];
    const void*  ei      = d_in[1];
    const float* ew      = (const float*)d_in[2];
    const float* lin1_w  = (const float*)d_in[3];
    const float* lin1_b  = (const float*)d_in[4];
    const float* lin2_w  = (const float*)d_in[5];
    const float* lin2_b  = (const float*)d_in[6];
    const float* norm_g  = (const float*)d_in[7];
    const float* norm_b  = (const float*)d_in[8];
    const float* conv_w  = (const float*)d_in[9];
    const float* conv_b  = (const float*)d_in[10];
    const float* fnorm_g = (const float*)d_in[11];
    const float* fnorm_b = (const float*)d_in[12];
    float*       out     = (float*)d_out;

    float  *h;
    __half *z;
    cudaGetSymbolAddress((void**)&h, g_h);
    cudaGetSymbolAddress((void**)&z, g_z);

    // One-time side stream + events (created outside graph capture: the
    // harness's first call is the uncaptured correctness run).
    static cudaStream_t s_csr = nullptr;
    static cudaEvent_t  ev_fork = nullptr, ev_csr = nullptr;
    if (s_csr == nullptr) {
        cudaStreamCreateWithFlags(&s_csr, cudaStreamNonBlocking);
        cudaEventCreateWithFlags(&ev_fork, cudaEventDisableTiming);
        cudaEventCreateWithFlags(&ev_csr, cudaEventDisableTiming);
    }

    const int GEMM_BX  = (NN + 127) / 128;   // 391
    const int ROW_BLKS = NN / 8;             // 6250
    const int E_BLKS   = (NEDGES + 255) / 256;
    const int N_BLKS   = (NN + 255) / 256;

    // Edge decode, then fork CSR build onto side stream
    detect_idx_kernel<<<1, 256>>>((const int*)ei);
    cudaEventRecord(ev_fork, 0);
    cudaStreamWaitEvent(s_csr, ev_fork, 0);

    zero_cnt_kernel<<<N_BLKS, 256, 0, s_csr>>>();
    hist_kernel<<<E_BLKS, 256, 0, s_csr>>>(ei);
    scan_partial_kernel<<<SCAN_BLKS, 256, 0, s_csr>>>();
    scan_blocks_kernel<<<1, 256, 0, s_csr>>>();
    scan_final_kernel<<<SCAN_BLKS, 256, 0, s_csr>>>();
    fill_kernel<<<E_BLKS, 256, 0, s_csr>>>(ei, ew);
    cudaEventRecord(ev_csr, s_csr);

    // Meanwhile on main stream: lin1 + first LN stats
    gemm_tf32_kernel<false, false><<<dim3(GEMM_BX, 2), 256>>>(
        x, IN_C, lin1_w, HID, lin1_b, h, HID, NN, nullptr, nullptr);
    ln_stats_kernel<<<ROW_BLKS, 256>>>(h, GC);

    // Join: gathers need the CSR
    cudaStreamWaitEvent(0, ev_csr, 0);

    for (int l = 0; l < NLAYERS; l++) {
        for (int g = 0; g < NGROUPS; g++) {
            int in_ofs  = (g == 0) ? GC : 0;
            int out_ofs = g * GC;
            int bidx = l * NGROUPS + g;

            gemm_tf32_kernel<true, true><<<dim3(GEMM_BX, 1), 256>>>(
                h + in_ofs, HID, conv_w + (size_t)bidx * GC * GC, GC, nullptr,
                z, GC, NN,
                norm_g + (size_t)bidx * GC, norm_b + (size_t)bidx * GC);
            gather_kernel<<<ROW_BLKS, 256>>>(z, conv_b + (size_t)bidx * GC, h, out_ofs);
        }
    }

    lin2_kernel<<<ROW_BLKS, 256>>>(h, fnorm_g, fnorm_b, lin2_w, lin2_b, out);
}

// round 8
// speedup vs baseline: 3.6272x; 1.1566x over previous
#include <cuda_runtime.h>
#include <cuda_fp16.h>
#include <cstdint>

#define NN      50000
#define IN_C    128
#define HID     256
#define OUT_C   40
#define NLAYERS 4
#define NGROUPS 2
#define GC      128
#define NEDGES  600000
#define LN_EPS  1e-5f
#define SCAN_BLKS 196   // 196*256 = 50176 >= NN

// Scratch (device globals: allocation-free)
__device__ float  g_h[(size_t)NN * HID];       // node features [N,256] fp32
__device__ __half g_z[(size_t)NN * GC];        // conv GEMM output [N,128] fp16
__device__ float2 g_stats[NN];                 // per-row (mu, rsigma) for next LN
__device__ __half g_wt1[HID * IN_C];           // lin1_w transposed [256][128] fp16
__device__ __half g_wtc[8 * GC * GC];          // conv_w transposed [8][n][k] fp16
__device__ int    g_cnt[NN];
__device__ int    g_cur[NN];
__device__ int    g_off[NN + 1];
__device__ int    g_part[SCAN_BLKS];
__device__ int2   g_csr[NEDGES];               // (src, bitcast fp32 weight) by dst
__device__ int    g_is64;

// Bitcast helper (the intrinsic __half2_as_uint does not exist)
__device__ __forceinline__ uint32_t h2_as_u32(__half2 h)
{
    return *reinterpret_cast<uint32_t*>(&h);
}

// ---------------------------------------------------------------------------
// Weight transpose: src fp32 [K][N] (batched) -> dst fp16 [N][K]
// ---------------------------------------------------------------------------
__global__ __launch_bounds__(256) void transpose_w_kernel(
    const float* __restrict__ src, __half* __restrict__ dst, int K, int N)
{
    __shared__ float tile[32][33];
    int b  = blockIdx.z;
    const float* s = src + (size_t)b * K * N;
    __half*      d = dst + (size_t)b * K * N;
    int k0 = blockIdx.y * 32, n0 = blockIdx.x * 32;
    int tx = threadIdx.x & 31, ty = threadIdx.x >> 5;  // ty 0..7
#pragma unroll
    for (int j = ty; j < 32; j += 8) {
        int k = k0 + j, n = n0 + tx;
        tile[j][tx] = (k < K && n < N) ? s[(size_t)k * N + n] : 0.f;
    }
    __syncthreads();
#pragma unroll
    for (int j = ty; j < 32; j += 8) {
        int n = n0 + j, k = k0 + tx;
        if (n < N && k < K) d[(size_t)n * K + k] = __float2half(tile[tx][j]);
    }
}

// ---------------------------------------------------------------------------
// Edge-index dtype detection (int64 vs int32)
// ---------------------------------------------------------------------------
__global__ void detect_idx_kernel(const int* __restrict__ ei32)
{
    __shared__ int nz;
    if (threadIdx.x == 0) nz = 0;
    __syncthreads();
    int bad = 0;
    for (int i = threadIdx.x; i < 2048; i += blockDim.x)
        if (ei32[2 * i + 1] != 0) bad = 1;
    if (bad) atomicOr(&nz, 1);
    __syncthreads();
    if (threadIdx.x == 0) g_is64 = (nz == 0) ? 1 : 0;
}

__device__ __forceinline__ int load_idx(const void* ei, int pos)
{
    if (g_is64) return (int)((const long long*)ei)[pos];
    return ((const int*)ei)[pos];
}

// ---------------------------------------------------------------------------
// CSR build: zero, hist, 3-phase parallel scan, fill
// ---------------------------------------------------------------------------
__global__ __launch_bounds__(256) void zero_cnt_kernel()
{
    int i = blockIdx.x * blockDim.x + threadIdx.x;
    if (i < NN) { g_cnt[i] = 0; g_cur[i] = 0; }
}

__global__ __launch_bounds__(256) void hist_kernel(const void* __restrict__ ei)
{
    int e = blockIdx.x * blockDim.x + threadIdx.x;
    if (e < NEDGES) atomicAdd(&g_cnt[load_idx(ei, NEDGES + e)], 1);
}

__global__ __launch_bounds__(256) void scan_partial_kernel()
{
    __shared__ int sm[256];
    int i = blockIdx.x * 256 + threadIdx.x;
    int v = (i < NN) ? g_cnt[i] : 0;
    sm[threadIdx.x] = v;
    __syncthreads();
#pragma unroll
    for (int o = 128; o; o >>= 1) {
        if (threadIdx.x < o) sm[threadIdx.x] += sm[threadIdx.x + o];
        __syncthreads();
    }
    if (threadIdx.x == 0) g_part[blockIdx.x] = sm[0];
}

__global__ __launch_bounds__(256) void scan_blocks_kernel()
{
    __shared__ int sm[256];
    int t = threadIdx.x;
    int v = (t < SCAN_BLKS) ? g_part[t] : 0;
    sm[t] = v;
    __syncthreads();
#pragma unroll
    for (int o = 1; o < 256; o <<= 1) {
        int u = (t >= o) ? sm[t - o] : 0;
        __syncthreads();
        sm[t] += u;
        __syncthreads();
    }
    if (t < SCAN_BLKS) g_part[t] = sm[t] - v;  // exclusive
}

__global__ __launch_bounds__(256) void scan_final_kernel()
{
    __shared__ int sm[256];
    int t = threadIdx.x;
    int i = blockIdx.x * 256 + t;
    int v = (i < NN) ? g_cnt[i] : 0;
    sm[t] = v;
    __syncthreads();
#pragma unroll
    for (int o = 1; o < 256; o <<= 1) {
        int u = (t >= o) ? sm[t - o] : 0;
        __syncthreads();
        sm[t] += u;
        __syncthreads();
    }
    if (i <= NN) g_off[i] = g_part[blockIdx.x] + sm[t] - v;
}

__global__ __launch_bounds__(256) void fill_kernel(
    const void* __restrict__ ei, const float* __restrict__ ew)
{
    int e = blockIdx.x * blockDim.x + threadIdx.x;
    if (e >= NEDGES) return;
    int srcv = load_idx(ei, e);
    int d    = load_idx(ei, NEDGES + e);
    int pos = g_off[d] + atomicAdd(&g_cur[d], 1);
    g_csr[pos] = make_int2(srcv, __float_as_int(ew[e]));
}

// ---------------------------------------------------------------------------
// fp16 tensor-core GEMM (fp32 accum), K fixed at 128. 128x128 block tile,
// 8 warps (4x2), 32x64 warp tile, K-tile 32, mma.m16n8k16, 2-stage smem
// double buffer (one __syncthreads per tile). A: fp32 gmem + fused LN+ReLU,
// converted to fp16. B: pre-transposed fp16 weights Wt[n][k], straight copy.
// Both smem tiles at 40-half pitch -> conflict-free fragment LDS.
// ---------------------------------------------------------------------------
#define P2 20   // pitch in half2 units (40 halves, 80 bytes)

__device__ __forceinline__ void mma_f16(float* c, const uint32_t* a,
                                        uint32_t b0, uint32_t b1)
{
    asm volatile(
        "mma.sync.aligned.m16n8k16.row.col.f32.f16.f16.f32 "
        "{%0,%1,%2,%3}, {%4,%5,%6,%7}, {%8,%9}, {%0,%1,%2,%3};"
        : "+f"(c[0]), "+f"(c[1]), "+f"(c[2]), "+f"(c[3])
        : "r"(a[0]), "r"(a[1]), "r"(a[2]), "r"(a[3]), "r"(b0), "r"(b1));
}

template<bool LN, bool HALF_OUT>
__global__ __launch_bounds__(256) void gemm_f16_kernel(
    const float* __restrict__ A, int lda,
    const __half* __restrict__ Wt,            // [n_total][128] fp16
    const float* __restrict__ bias, void* __restrict__ Cv, int ldc,
    int nrows,
    const float* __restrict__ gamma, const float* __restrict__ beta)
{
    __shared__ uint32_t As2[2][128 * P2];
    __shared__ uint32_t Bs2[2][128 * P2];

    const int tid  = threadIdx.x;
    const int wid  = tid >> 5;
    const int lane = tid & 31;
    const int gid  = lane >> 2;
    const int tig  = lane & 3;
    const int wm   = (wid & 3) * 32;
    const int wn   = (wid >> 2) * 64;
    const int rowblk = blockIdx.x * 128;
    const int colblk = blockIdx.y * 128;

    float c[2][8][4];
#pragma unroll
    for (int mt = 0; mt < 2; mt++)
#pragma unroll
        for (int nt = 0; nt < 8; nt++)
#pragma unroll
            for (int r = 0; r < 4; r++) c[mt][nt][r] = 0.f;

    uint32_t ra[4][2];   // A staging: 4 chunks x 2 half2
    uint4    rb[2];      // B staging: 2 x 8 halves

    auto load_regs = [&](int kt) {
#pragma unroll
        for (int i = 0; i < 4; i++) {
            int q  = tid + i * 256;
            int r  = q >> 3;
            int c4 = (q & 7) * 4;
            int grow = rowblk + r;
            float4 v = make_float4(0.f, 0.f, 0.f, 0.f);
            if (grow < nrows) {
                v = *(const float4*)(A + (size_t)grow * lda + kt + c4);
                if (LN) {
                    float2 st = g_stats[grow];
                    float4 g4 = *(const float4*)(gamma + kt + c4);
                    float4 b4 = *(const float4*)(beta + kt + c4);
                    v.x = fmaxf((v.x - st.x) * st.y * g4.x + b4.x, 0.f);
                    v.y = fmaxf((v.y - st.x) * st.y * g4.y + b4.y, 0.f);
                    v.z = fmaxf((v.z - st.x) * st.y * g4.z + b4.z, 0.f);
                    v.w = fmaxf((v.w - st.x) * st.y * g4.w + b4.w, 0.f);
                }
            }
            ra[i][0] = h2_as_u32(__floats2half2_rn(v.x, v.y));
            ra[i][1] = h2_as_u32(__floats2half2_rn(v.z, v.w));
        }
#pragma unroll
        for (int i = 0; i < 2; i++) {
            int q   = tid + i * 256;
            int n   = q >> 2;
            int kh8 = (q & 3) * 8;
            rb[i] = *(const uint4*)(Wt + (size_t)(colblk + n) * 128 + kt + kh8);
        }
    };

    auto store_smem = [&](int buf) {
#pragma unroll
        for (int i = 0; i < 4; i++) {
            int q  = tid + i * 256;
            int r  = q >> 3;
            int c4 = (q & 7) * 4;
            As2[buf][r * P2 + (c4 >> 1)]     = ra[i][0];
            As2[buf][r * P2 + (c4 >> 1) + 1] = ra[i][1];
        }
#pragma unroll
        for (int i = 0; i < 2; i++) {
            int q   = tid + i * 256;
            int n   = q >> 2;
            int kh8 = (q & 3) * 8;
            *(uint4*)&Bs2[buf][n * P2 + (kh8 >> 1)] = rb[i];
        }
    };

    auto compute = [&](int buf) {
#pragma unroll
        for (int ks = 0; ks < 2; ks++) {
            int kh = ks * 8;
            uint32_t a[2][4];
#pragma unroll
            for (int mt = 0; mt < 2; mt++) {
                int m = wm + mt * 16 + gid;
                a[mt][0] = As2[buf][m * P2 + kh + tig];
                a[mt][1] = As2[buf][(m + 8) * P2 + kh + tig];
                a[mt][2] = As2[buf][m * P2 + kh + tig + 4];
                a[mt][3] = As2[buf][(m + 8) * P2 + kh + tig + 4];
            }
#pragma unroll
            for (int nt = 0; nt < 8; nt++) {
                int n = wn + nt * 8 + gid;
                uint32_t b0 = Bs2[buf][n * P2 + kh + tig];
                uint32_t b1 = Bs2[buf][n * P2 + kh + tig + 4];
                mma_f16(c[0][nt], a[0], b0, b1);
                mma_f16(c[1][nt], a[1], b0, b1);
            }
        }
    };

    load_regs(0);
    store_smem(0);
    __syncthreads();
#pragma unroll
    for (int t = 0; t < 4; t++) {
        if (t < 3) load_regs((t + 1) * 32);    // gmem latency overlaps mma
        compute(t & 1);
        if (t < 3) {
            store_smem((t + 1) & 1);           // opposite buffer: race-free
            __syncthreads();
        }
    }

#pragma unroll
    for (int mt = 0; mt < 2; mt++) {
        int row0 = rowblk + wm + mt * 16 + gid;
        int row1 = row0 + 8;
#pragma unroll
        for (int nt = 0; nt < 8; nt++) {
            int col = colblk + wn + nt * 8 + 2 * tig;
            float bx = 0.f, by = 0.f;
            if (bias != nullptr) { bx = bias[col]; by = bias[col + 1]; }
            if (HALF_OUT) {
                __half* C = (__half*)Cv;
                if (row0 < nrows)
                    *(__half2*)(C + (size_t)row0 * ldc + col) =
                        __floats2half2_rn(c[mt][nt][0] + bx, c[mt][nt][1] + by);
                if (row1 < nrows)
                    *(__half2*)(C + (size_t)row1 * ldc + col) =
                        __floats2half2_rn(c[mt][nt][2] + bx, c[mt][nt][3] + by);
            } else {
                float* C = (float*)Cv;
                if (row0 < nrows)
                    *(float2*)(C + (size_t)row0 * ldc + col) =
                        make_float2(c[mt][nt][0] + bx, c[mt][nt][1] + by);
                if (row1 < nrows)
                    *(float2*)(C + (size_t)row1 * ldc + col) =
                        make_float2(c[mt][nt][2] + bx, c[mt][nt][3] + by);
            }
        }
    }
}

// ---------------------------------------------------------------------------
// Standalone LN stats (only after lin1)
// ---------------------------------------------------------------------------
__global__ __launch_bounds__(256) void ln_stats_kernel(
    const float* __restrict__ h, int colofs)
{
    int row = blockIdx.x * 8 + (threadIdx.x >> 5);
    int lane = threadIdx.x & 31;
    if (row >= NN) return;
    float4 v = ((const float4*)(h + (size_t)row * HID + colofs))[lane];
    float s  = v.x + v.y + v.z + v.w;
    float sq = v.x * v.x + v.y * v.y + v.z * v.z + v.w * v.w;
#pragma unroll
    for (int o = 16; o; o >>= 1) {
        s  += __shfl_xor_sync(0xffffffffu, s, o);
        sq += __shfl_xor_sync(0xffffffffu, sq, o);
    }
    if (lane == 0) {
        float mu  = s * (1.f / 128.f);
        float var = sq * (1.f / 128.f) - mu * mu;
        g_stats[row] = make_float2(mu, rsqrtf(var + LN_EPS));
    }
}

// ---------------------------------------------------------------------------
// CSR gather (fp16 z) + bias + in-place h update + next-LN stats
// ---------------------------------------------------------------------------
__device__ __forceinline__ void acc_edge(float4& acc, const __half* z,
                                         int2 m, int lane)
{
    float w = __int_as_float(m.y);
    uint2 u = *(const uint2*)(z + (size_t)m.x * GC + lane * 4);
    float2 lo = __half22float2(*(const __half2*)&u.x);
    float2 hi = __half22float2(*(const __half2*)&u.y);
    acc.x = fmaf(w, lo.x, acc.x); acc.y = fmaf(w, lo.y, acc.y);
    acc.z = fmaf(w, hi.x, acc.z); acc.w = fmaf(w, hi.y, acc.w);
}

__global__ __launch_bounds__(256) void gather_kernel(
    const __half* __restrict__ z, const float* __restrict__ bias,
    float* __restrict__ h, int out_ofs)
{
    int row = blockIdx.x * 8 + (threadIdx.x >> 5);
    int lane = threadIdx.x & 31;
    if (row >= NN) return;

    float4 acc = ((const float4*)bias)[lane];
    int s = g_off[row], e = g_off[row + 1];

    int i = s;
    for (; i + 4 <= e; i += 4) {
        int2 m0 = g_csr[i];
        int2 m1 = g_csr[i + 1];
        int2 m2 = g_csr[i + 2];
        int2 m3 = g_csr[i + 3];
        acc_edge(acc, z, m0, lane);
        acc_edge(acc, z, m1, lane);
        acc_edge(acc, z, m2, lane);
        acc_edge(acc, z, m3, lane);
    }
    for (; i < e; i++)
        acc_edge(acc, z, g_csr[i], lane);

    float4* hp = (float4*)(h + (size_t)row * HID + out_ofs);
    float4 hv = hp[lane];
    hv.x += acc.x; hv.y += acc.y; hv.z += acc.z; hv.w += acc.w;
    hp[lane] = hv;

    float sm = hv.x + hv.y + hv.z + hv.w;
    float sq = hv.x * hv.x + hv.y * hv.y + hv.z * hv.z + hv.w * hv.w;
#pragma unroll
    for (int o = 16; o; o >>= 1) {
        sm += __shfl_xor_sync(0xffffffffu, sm, o);
        sq += __shfl_xor_sync(0xffffffffu, sq, o);
    }
    if (lane == 0) {
        float mu  = sm * (1.f / 128.f);
        float var = sq * (1.f / 128.f) - mu * mu;
        g_stats[row] = make_float2(mu, rsqrtf(var + LN_EPS));
    }
}

// ---------------------------------------------------------------------------
// lin2 with fused final LayerNorm+ReLU
// ---------------------------------------------------------------------------
__global__ __launch_bounds__(256) void lin2_kernel(
    const float* __restrict__ h,
    const float* __restrict__ gamma, const float* __restrict__ beta,
    const float* __restrict__ W, const float* __restrict__ b,
    float* __restrict__ out)
{
    __shared__ float ws[OUT_C * HID];
    int tid = threadIdx.x;
    for (int i = tid; i < OUT_C * HID; i += 256) {
        int c = i >> 8;
        int k = i & 255;
        ws[i] = W[k * OUT_C + c];
    }
    __syncthreads();

    int row = blockIdx.x * 8 + (tid >> 5);
    int lane = tid & 31;
    if (row >= NN) return;

    const float4* fp = (const float4*)(h + (size_t)row * HID);
    float4 a  = fp[lane];
    float4 bb = fp[lane + 32];

    float s  = a.x + a.y + a.z + a.w + bb.x + bb.y + bb.z + bb.w;
    float sq = a.x * a.x + a.y * a.y + a.z * a.z + a.w * a.w
             + bb.x * bb.x + bb.y * bb.y + bb.z * bb.z + bb.w * bb.w;
#pragma unroll
    for (int o = 16; o; o >>= 1) {
        s  += __shfl_xor_sync(0xffffffffu, s, o);
        sq += __shfl_xor_sync(0xffffffffu, sq, o);
    }
    float mu  = s * (1.f / 256.f);
    float var = sq * (1.f / 256.f) - mu * mu;
    float rs  = rsqrtf(var + LN_EPS);

    float4 g0 = ((const float4*)gamma)[lane];
    float4 g1 = ((const float4*)gamma)[lane + 32];
    float4 b0 = ((const float4*)beta)[lane];
    float4 b1 = ((const float4*)beta)[lane + 32];
    a.x  = fmaxf((a.x  - mu) * rs * g0.x + b0.x, 0.f);
    a.y  = fmaxf((a.y  - mu) * rs * g0.y + b0.y, 0.f);
    a.z  = fmaxf((a.z  - mu) * rs * g0.z + b0.z, 0.f);
    a.w  = fmaxf((a.w  - mu) * rs * g0.w + b0.w, 0.f);
    bb.x = fmaxf((bb.x - mu) * rs * g1.x + b1.x, 0.f);
    bb.y = fmaxf((bb.y - mu) * rs * g1.y + b1.y, 0.f);
    bb.z = fmaxf((bb.z - mu) * rs * g1.z + b1.z, 0.f);
    bb.w = fmaxf((bb.w - mu) * rs * g1.w + b1.w, 0.f);

    int k0 = lane * 4;
#pragma unroll 4
    for (int c = 0; c < OUT_C; c++) {
        const float* wc = ws + c * HID;
        float p = a.x * wc[k0] + a.y * wc[k0 + 1] + a.z * wc[k0 + 2] + a.w * wc[k0 + 3]
                + bb.x * wc[128 + k0] + bb.y * wc[128 + k0 + 1]
                + bb.z * wc[128 + k0 + 2] + bb.w * wc[128 + k0 + 3];
#pragma unroll
        for (int o = 16; o; o >>= 1) p += __shfl_xor_sync(0xffffffffu, p, o);
        if (lane == 0) out[(size_t)row * OUT_C + c] = p + b[c];
    }
}

// ---------------------------------------------------------------------------
extern "C" void kernel_launch(void* const* d_in, const int* in_sizes, int n_in,
                              void* d_out, int out_size)
{
    const float* x       = (const float*)d_in[0];
    const void*  ei      = d_in[1];
    const float* ew      = (const float*)d_in[2];
    const float* lin1_w  = (const float*)d_in[3];
    const float* lin1_b  = (const float*)d_in[4];
    const float* lin2_w  = (const float*)d_in[5];
    const float* lin2_b  = (const float*)d_in[6];
    const float* norm_g  = (const float*)d_in[7];
    const float* norm_b  = (const float*)d_in[8];
    const float* conv_w  = (const float*)d_in[9];
    const float* conv_b  = (const float*)d_in[10];
    const float* fnorm_g = (const float*)d_in[11];
    const float* fnorm_b = (const float*)d_in[12];
    float*       out     = (float*)d_out;

    float  *h;
    __half *z, *wt1, *wtc;
    cudaGetSymbolAddress((void**)&h, g_h);
    cudaGetSymbolAddress((void**)&z, g_z);
    cudaGetSymbolAddress((void**)&wt1, g_wt1);
    cudaGetSymbolAddress((void**)&wtc, g_wtc);

    static cudaStream_t s_csr = nullptr;
    static cudaEvent_t  ev_fork = nullptr, ev_csr = nullptr;
    if (s_csr == nullptr) {
        cudaStreamCreateWithFlags(&s_csr, cudaStreamNonBlocking);
        cudaEventCreateWithFlags(&ev_fork, cudaEventDisableTiming);
        cudaEventCreateWithFlags(&ev_csr, cudaEventDisableTiming);
    }

    const int GEMM_BX  = (NN + 127) / 128;   // 391
    const int ROW_BLKS = NN / 8;             // 6250
    const int E_BLKS   = (NEDGES + 255) / 256;
    const int N_BLKS   = (NN + 255) / 256;

    // Fork CSR build onto side stream (needs only ei/ew)
    detect_idx_kernel<<<1, 256>>>((const int*)ei);
    cudaEventRecord(ev_fork, 0);
    cudaStreamWaitEvent(s_csr, ev_fork, 0);
    zero_cnt_kernel<<<N_BLKS, 256, 0, s_csr>>>();
    hist_kernel<<<E_BLKS, 256, 0, s_csr>>>(ei);
    scan_partial_kernel<<<SCAN_BLKS, 256, 0, s_csr>>>();
    scan_blocks_kernel<<<1, 256, 0, s_csr>>>();
    scan_final_kernel<<<SCAN_BLKS, 256, 0, s_csr>>>();
    fill_kernel<<<E_BLKS, 256, 0, s_csr>>>(ei, ew);
    cudaEventRecord(ev_csr, s_csr);

    // Main stream: weight transposes (tiny), lin1, first LN stats
    transpose_w_kernel<<<dim3(HID / 32, IN_C / 32, 1), 256>>>(lin1_w, wt1, IN_C, HID);
    transpose_w_kernel<<<dim3(GC / 32, GC / 32, 8), 256>>>(conv_w, wtc, GC, GC);

    gemm_f16_kernel<false, false><<<dim3(GEMM_BX, 2), 256>>>(
        x, IN_C, wt1, lin1_b, h, HID, NN, nullptr, nullptr);
    ln_stats_kernel<<<ROW_BLKS, 256>>>(h, GC);

    // Join: gathers need the CSR
    cudaStreamWaitEvent(0, ev_csr, 0);

    for (int l = 0; l < NLAYERS; l++) {
        for (int g = 0; g < NGROUPS; g++) {
            int in_ofs  = (g == 0) ? GC : 0;
            int out_ofs = g * GC;
            int bidx = l * NGROUPS + g;

            gemm_f16_kernel<true, true><<<dim3(GEMM_BX, 1), 256>>>(
                h + in_ofs, HID, wtc + (size_t)bidx * GC * GC, nullptr,
                z, GC, NN,
                norm_g + (size_t)bidx * GC, norm_b + (size_t)bidx * GC);
            gather_kernel<<<ROW_BLKS, 256>>>(z, conv_b + (size_t)bidx * GC, h, out_ofs);
        }
    }

    lin2_kernel<<<ROW_BLKS, 256>>>(h, fnorm_g, fnorm_b, lin2_w, lin2_b, out);
}

// round 9
// speedup vs baseline: 5.2963x; 1.4602x over previous
#include <cuda_runtime.h>
#include <cuda_fp16.h>
#include <cstdint>

#define NN      50000
#define IN_C    128
#define HID     256
#define OUT_C   40
#define NLAYERS 4
#define NGROUPS 2
#define GC      128
#define NEDGES  600000
#define LN_EPS  1e-5f
#define SCAN_BLKS 196   // 196*256 = 50176 >= NN

// Scratch (device globals: allocation-free)
__device__ float  g_h[(size_t)NN * HID];       // node features [N,256] fp32
__device__ __half g_z[(size_t)NN * GC];        // conv GEMM output [N,128] fp16
__device__ float2 g_stats[NN];                 // per-row (mu, rsigma) for next LN
__device__ __half g_wt1[HID * IN_C];           // lin1_w transposed [256][128] fp16
__device__ __half g_wtc[8 * GC * GC];          // conv_w transposed [8][n][k] fp16
__device__ __half g_wt2[128 * HID];            // lin2_w transposed [40->128 pad][256] fp16 (pad rows stay 0)
__device__ int    g_cnt[NN];
__device__ int    g_cur[NN];
__device__ int    g_off[NN + 1];
__device__ int    g_part[SCAN_BLKS];
__device__ int2   g_csr[NEDGES];               // (src, bitcast fp32 weight) by dst
__device__ int    g_is64;

__device__ __forceinline__ uint32_t h2_as_u32(__half2 h)
{
    return *reinterpret_cast<uint32_t*>(&h);
}

// ---------------------------------------------------------------------------
// Weight transpose: src fp32 [K][N] (batched) -> dst fp16 [N][K]
// ---------------------------------------------------------------------------
__global__ __launch_bounds__(256) void transpose_w_kernel(
    const float* __restrict__ src, __half* __restrict__ dst, int K, int N)
{
    __shared__ float tile[32][33];
    int b  = blockIdx.z;
    const float* s = src + (size_t)b * K * N;
    __half*      d = dst + (size_t)b * K * N;
    int k0 = blockIdx.y * 32, n0 = blockIdx.x * 32;
    int tx = threadIdx.x & 31, ty = threadIdx.x >> 5;
#pragma unroll
    for (int j = ty; j < 32; j += 8) {
        int k = k0 + j, n = n0 + tx;
        tile[j][tx] = (k < K && n < N) ? s[(size_t)k * N + n] : 0.f;
    }
    __syncthreads();
#pragma unroll
    for (int j = ty; j < 32; j += 8) {
        int n = n0 + j, k = k0 + tx;
        if (n < N && k < K) d[(size_t)n * K + k] = __float2half(tile[tx][j]);
    }
}

// ---------------------------------------------------------------------------
// Edge-index dtype detection (int64 vs int32)
// ---------------------------------------------------------------------------
__global__ void detect_idx_kernel(const int* __restrict__ ei32)
{
    __shared__ int nz;
    if (threadIdx.x == 0) nz = 0;
    __syncthreads();
    int bad = 0;
    for (int i = threadIdx.x; i < 2048; i += blockDim.x)
        if (ei32[2 * i + 1] != 0) bad = 1;
    if (bad) atomicOr(&nz, 1);
    __syncthreads();
    if (threadIdx.x == 0) g_is64 = (nz == 0) ? 1 : 0;
}

__device__ __forceinline__ int load_idx(const void* ei, int pos)
{
    if (g_is64) return (int)((const long long*)ei)[pos];
    return ((const int*)ei)[pos];
}

// ---------------------------------------------------------------------------
// CSR build
// ---------------------------------------------------------------------------
__global__ __launch_bounds__(256) void zero_cnt_kernel()
{
    int i = blockIdx.x * blockDim.x + threadIdx.x;
    if (i < NN) { g_cnt[i] = 0; g_cur[i] = 0; }
}

__global__ __launch_bounds__(256) void hist_kernel(const void* __restrict__ ei)
{
    int e = blockIdx.x * blockDim.x + threadIdx.x;
    if (e < NEDGES) atomicAdd(&g_cnt[load_idx(ei, NEDGES + e)], 1);
}

__global__ __launch_bounds__(256) void scan_partial_kernel()
{
    __shared__ int sm[256];
    int i = blockIdx.x * 256 + threadIdx.x;
    int v = (i < NN) ? g_cnt[i] : 0;
    sm[threadIdx.x] = v;
    __syncthreads();
#pragma unroll
    for (int o = 128; o; o >>= 1) {
        if (threadIdx.x < o) sm[threadIdx.x] += sm[threadIdx.x + o];
        __syncthreads();
    }
    if (threadIdx.x == 0) g_part[blockIdx.x] = sm[0];
}

__global__ __launch_bounds__(256) void scan_blocks_kernel()
{
    __shared__ int sm[256];
    int t = threadIdx.x;
    int v = (t < SCAN_BLKS) ? g_part[t] : 0;
    sm[t] = v;
    __syncthreads();
#pragma unroll
    for (int o = 1; o < 256; o <<= 1) {
        int u = (t >= o) ? sm[t - o] : 0;
        __syncthreads();
        sm[t] += u;
        __syncthreads();
    }
    if (t < SCAN_BLKS) g_part[t] = sm[t] - v;  // exclusive
}

__global__ __launch_bounds__(256) void scan_final_kernel()
{
    __shared__ int sm[256];
    int t = threadIdx.x;
    int i = blockIdx.x * 256 + t;
    int v = (i < NN) ? g_cnt[i] : 0;
    sm[t] = v;
    __syncthreads();
#pragma unroll
    for (int o = 1; o < 256; o <<= 1) {
        int u = (t >= o) ? sm[t - o] : 0;
        __syncthreads();
        sm[t] += u;
        __syncthreads();
    }
    if (i <= NN) g_off[i] = g_part[blockIdx.x] + sm[t] - v;
}

__global__ __launch_bounds__(256) void fill_kernel(
    const void* __restrict__ ei, const float* __restrict__ ew)
{
    int e = blockIdx.x * blockDim.x + threadIdx.x;
    if (e >= NEDGES) return;
    int srcv = load_idx(ei, e);
    int d    = load_idx(ei, NEDGES + e);
    int pos = g_off[d] + atomicAdd(&g_cur[d], 1);
    g_csr[pos] = make_int2(srcv, __float_as_int(ew[e]));
}

// ---------------------------------------------------------------------------
// Weight-resident persistent fp16 GEMM (fp32 accum), K = KD (128 or 256).
// B (128 x KD fp16, pre-transposed [n][k]) loaded to smem ONCE per block;
// block loops over 128-row blocks with a full-K A double buffer -> exactly
// one __syncthreads per row-block. Fused LN+ReLU on A (stats in g_stats).
// Row pitch KD/2+4 u32 -> conflict-free fragment LDS (pitch mod 32 == 4).
// ---------------------------------------------------------------------------
__device__ __forceinline__ void mma_f16(float* c, const uint32_t* a,
                                        uint32_t b0, uint32_t b1)
{
    asm volatile(
        "mma.sync.aligned.m16n8k16.row.col.f32.f16.f16.f32 "
        "{%0,%1,%2,%3}, {%4,%5,%6,%7}, {%8,%9}, {%0,%1,%2,%3};"
        : "+f"(c[0]), "+f"(c[1]), "+f"(c[2]), "+f"(c[3])
        : "r"(a[0]), "r"(a[1]), "r"(a[2]), "r"(a[3]), "r"(b0), "r"(b1));
}

template<bool LN, bool HALF_OUT, int KD>
__global__ __launch_bounds__(256, KD == 128 ? 2 : 1) void gemm_f16_kernel(
    const float* __restrict__ A, int lda,
    const __half* __restrict__ Wt,            // [>=colblk+128][KD] fp16
    const float* __restrict__ bias, void* __restrict__ Cv, int ldc,
    int nrows, int ncol_lim,
    const float* __restrict__ gamma, const float* __restrict__ beta)
{
    constexpr int PF = KD / 2 + 4;            // u32 pitch per row
    constexpr int AI = KD / 8;                // A float4 chunks per thread
    constexpr int BI = KD / 16;               // B uint4 chunks per thread

    extern __shared__ uint32_t smem[];
    uint32_t* Bs  = smem;                     // 128*PF
    uint32_t* As0 = smem + 128 * PF;
    uint32_t* As1 = As0 + 128 * PF;

    const int tid  = threadIdx.x;
    const int wid  = tid >> 5;
    const int lane = tid & 31;
    const int gid  = lane >> 2;
    const int tig  = lane & 3;
    const int wm   = (wid & 3) * 32;
    const int wn   = (wid >> 2) * 64;
    const int colblk = blockIdx.y * 128;
    const int NRB  = (nrows + 127) >> 7;

    // ---- B resident load (once) ----
#pragma unroll
    for (int i = 0; i < BI; i++) {
        int q   = tid + i * 256;
        int n   = q / (KD / 8);
        int kh8 = (q % (KD / 8)) * 8;
        uint4 v = *(const uint4*)(Wt + (size_t)(colblk + n) * KD + kh8);
        *(uint4*)&Bs[n * PF + (kh8 >> 1)] = v;
    }

    uint32_t ra[AI][2];

    auto loadA = [&](int rb) {
        int rowblk = rb * 128;
#pragma unroll
        for (int i = 0; i < AI; i++) {
            int q  = tid + i * 256;
            int r  = q / (KD / 4);
            int c4 = (q % (KD / 4)) * 4;
            int grow = rowblk + r;
            float4 v = make_float4(0.f, 0.f, 0.f, 0.f);
            if (grow < nrows) {
                v = *(const float4*)(A + (size_t)grow * lda + c4);
                if (LN) {
                    float2 st = g_stats[grow];
                    float4 g4 = *(const float4*)(gamma + c4);
                    float4 b4 = *(const float4*)(beta + c4);
                    v.x = fmaxf((v.x - st.x) * st.y * g4.x + b4.x, 0.f);
                    v.y = fmaxf((v.y - st.x) * st.y * g4.y + b4.y, 0.f);
                    v.z = fmaxf((v.z - st.x) * st.y * g4.z + b4.z, 0.f);
                    v.w = fmaxf((v.w - st.x) * st.y * g4.w + b4.w, 0.f);
                }
            }
            ra[i][0] = h2_as_u32(__floats2half2_rn(v.x, v.y));
            ra[i][1] = h2_as_u32(__floats2half2_rn(v.z, v.w));
        }
    };

    auto storeA = [&](uint32_t* As) {
#pragma unroll
        for (int i = 0; i < AI; i++) {
            int q  = tid + i * 256;
            int r  = q / (KD / 4);
            int c4 = (q % (KD / 4)) * 4;
            *(uint2*)&As[r * PF + (c4 >> 1)] = make_uint2(ra[i][0], ra[i][1]);
        }
    };

    float c[2][8][4];

    int rb = blockIdx.x;
    if (rb >= NRB) return;
    loadA(rb);
    storeA(As0);
    __syncthreads();

    int buf = 0;
    for (;;) {
        int rb_next = rb + gridDim.x;
        bool more = rb_next < NRB;
        if (more) loadA(rb_next);   // gmem latency overlaps MMA below

        // zero accumulators
#pragma unroll
        for (int mt = 0; mt < 2; mt++)
#pragma unroll
            for (int nt = 0; nt < 8; nt++)
#pragma unroll
                for (int r = 0; r < 4; r++) c[mt][nt][r] = 0.f;

        uint32_t* As = buf ? As1 : As0;
#pragma unroll
        for (int ks = 0; ks < KD / 16; ks++) {
            int kh = ks * 8;
            uint32_t a[2][4];
#pragma unroll
            for (int mt = 0; mt < 2; mt++) {
                int m = wm + mt * 16 + gid;
                a[mt][0] = As[m * PF + kh + tig];
                a[mt][1] = As[(m + 8) * PF + kh + tig];
                a[mt][2] = As[m * PF + kh + tig + 4];
                a[mt][3] = As[(m + 8) * PF + kh + tig + 4];
            }
#pragma unroll
            for (int nt = 0; nt < 8; nt++) {
                int n = wn + nt * 8 + gid;
                uint32_t b0 = Bs[n * PF + kh + tig];
                uint32_t b1 = Bs[n * PF + kh + tig + 4];
                mma_f16(c[0][nt], a[0], b0, b1);
                mma_f16(c[1][nt], a[1], b0, b1);
            }
        }

        // epilogue for this row-block
        int rowblk = rb * 128;
#pragma unroll
        for (int mt = 0; mt < 2; mt++) {
            int row0 = rowblk + wm + mt * 16 + gid;
            int row1 = row0 + 8;
#pragma unroll
            for (int nt = 0; nt < 8; nt++) {
                int col = colblk + wn + nt * 8 + 2 * tig;
                if (col >= ncol_lim) continue;
                float bx = 0.f, by = 0.f;
                if (bias != nullptr) { bx = bias[col]; by = bias[col + 1]; }
                if (HALF_OUT) {
                    __half* C = (__half*)Cv;
                    if (row0 < nrows)
                        *(__half2*)(C + (size_t)row0 * ldc + col) =
                            __floats2half2_rn(c[mt][nt][0] + bx, c[mt][nt][1] + by);
                    if (row1 < nrows)
                        *(__half2*)(C + (size_t)row1 * ldc + col) =
                            __floats2half2_rn(c[mt][nt][2] + bx, c[mt][nt][3] + by);
                } else {
                    float* C = (float*)Cv;
                    if (row0 < nrows)
                        *(float2*)(C + (size_t)row0 * ldc + col) =
                            make_float2(c[mt][nt][0] + bx, c[mt][nt][1] + by);
                    if (row1 < nrows)
                        *(float2*)(C + (size_t)row1 * ldc + col) =
                            make_float2(c[mt][nt][2] + bx, c[mt][nt][3] + by);
                }
            }
        }

        if (!more) break;
        buf ^= 1;
        storeA(buf ? As1 : As0);
        __syncthreads();
        rb = rb_next;
    }
}

// ---------------------------------------------------------------------------
// Standalone LN stats (only after lin1)
// ---------------------------------------------------------------------------
__global__ __launch_bounds__(256) void ln_stats_kernel(
    const float* __restrict__ h, int colofs)
{
    int row = blockIdx.x * 8 + (threadIdx.x >> 5);
    int lane = threadIdx.x & 31;
    if (row >= NN) return;
    float4 v = ((const float4*)(h + (size_t)row * HID + colofs))[lane];
    float s  = v.x + v.y + v.z + v.w;
    float sq = v.x * v.x + v.y * v.y + v.z * v.z + v.w * v.w;
#pragma unroll
    for (int o = 16; o; o >>= 1) {
        s  += __shfl_xor_sync(0xffffffffu, s, o);
        sq += __shfl_xor_sync(0xffffffffu, sq, o);
    }
    if (lane == 0) {
        float mu  = s * (1.f / 128.f);
        float var = sq * (1.f / 128.f) - mu * mu;
        g_stats[row] = make_float2(mu, rsqrtf(var + LN_EPS));
    }
}

// ---------------------------------------------------------------------------
// CSR gather (fp16 z) + bias + in-place h update + next-LN stats.
// FULLSTATS: produce 256-wide stats (for the final LayerNorm before lin2).
// ---------------------------------------------------------------------------
__device__ __forceinline__ void acc_edge(float4& acc, const __half* z,
                                         int2 m, int lane)
{
    float w = __int_as_float(m.y);
    uint2 u = *(const uint2*)(z + (size_t)m.x * GC + lane * 4);
    float2 lo = __half22float2(*(const __half2*)&u.x);
    float2 hi = __half22float2(*(const __half2*)&u.y);
    acc.x = fmaf(w, lo.x, acc.x); acc.y = fmaf(w, lo.y, acc.y);
    acc.z = fmaf(w, hi.x, acc.z); acc.w = fmaf(w, hi.y, acc.w);
}

template<bool FULLSTATS>
__global__ __launch_bounds__(256) void gather_kernel(
    const __half* __restrict__ z, const float* __restrict__ bias,
    float* __restrict__ h, int out_ofs)
{
    int row = blockIdx.x * 8 + (threadIdx.x >> 5);
    int lane = threadIdx.x & 31;
    if (row >= NN) return;

    float4 acc = ((const float4*)bias)[lane];
    int s = g_off[row], e = g_off[row + 1];

    int i = s;
    for (; i + 4 <= e; i += 4) {
        int2 m0 = g_csr[i];
        int2 m1 = g_csr[i + 1];
        int2 m2 = g_csr[i + 2];
        int2 m3 = g_csr[i + 3];
        acc_edge(acc, z, m0, lane);
        acc_edge(acc, z, m1, lane);
        acc_edge(acc, z, m2, lane);
        acc_edge(acc, z, m3, lane);
    }
    for (; i < e; i++)
        acc_edge(acc, z, g_csr[i], lane);

    float4* hp = (float4*)(h + (size_t)row * HID + out_ofs);
    float4 hv = hp[lane];
    hv.x += acc.x; hv.y += acc.y; hv.z += acc.z; hv.w += acc.w;
    hp[lane] = hv;

    float sm = hv.x + hv.y + hv.z + hv.w;
    float sq = hv.x * hv.x + hv.y * hv.y + hv.z * hv.z + hv.w * hv.w;
    float inv = 1.f / 128.f;
    if (FULLSTATS) {
        // also fold in the other 128-col half (already final)
        const float4* op = (const float4*)(h + (size_t)row * HID + (out_ofs ^ GC));
        float4 ov = op[lane];
        sm += ov.x + ov.y + ov.z + ov.w;
        sq += ov.x * ov.x + ov.y * ov.y + ov.z * ov.z + ov.w * ov.w;
        inv = 1.f / 256.f;
    }
#pragma unroll
    for (int o = 16; o; o >>= 1) {
        sm += __shfl_xor_sync(0xffffffffu, sm, o);
        sq += __shfl_xor_sync(0xffffffffu, sq, o);
    }
    if (lane == 0) {
        float mu  = sm * inv;
        float var = sq * inv - mu * mu;
        g_stats[row] = make_float2(mu, rsqrtf(var + LN_EPS));
    }
}

// ---------------------------------------------------------------------------
extern "C" void kernel_launch(void* const* d_in, const int* in_sizes, int n_in,
                              void* d_out, int out_size)
{
    const float* x       = (const float*)d_in[0];
    const void*  ei      = d_in[1];
    const float* ew      = (const float*)d_in[2];
    const float* lin1_w  = (const float*)d_in[3];
    const float* lin1_b  = (const float*)d_in[4];
    const float* lin2_w  = (const float*)d_in[5];
    const float* lin2_b  = (const float*)d_in[6];
    const float* norm_g  = (const float*)d_in[7];
    const float* norm_b  = (const float*)d_in[8];
    const float* conv_w  = (const float*)d_in[9];
    const float* conv_b  = (const float*)d_in[10];
    const float* fnorm_g = (const float*)d_in[11];
    const float* fnorm_b = (const float*)d_in[12];
    float*       out     = (float*)d_out;

    float  *h;
    __half *z, *wt1, *wtc, *wt2;
    cudaGetSymbolAddress((void**)&h, g_h);
    cudaGetSymbolAddress((void**)&z, g_z);
    cudaGetSymbolAddress((void**)&wt1, g_wt1);
    cudaGetSymbolAddress((void**)&wtc, g_wtc);
    cudaGetSymbolAddress((void**)&wt2, g_wt2);

    const int SMEM128 = 3 * 128 * (128 / 2 + 4) * 4;   // 104448 B
    const int SMEM256 = 3 * 128 * (256 / 2 + 4) * 4;   // 202752 B

    static cudaStream_t s_csr = nullptr;
    static cudaEvent_t  ev_fork = nullptr, ev_csr = nullptr;
    if (s_csr == nullptr) {
        cudaStreamCreateWithFlags(&s_csr, cudaStreamNonBlocking);
        cudaEventCreateWithFlags(&ev_fork, cudaEventDisableTiming);
        cudaEventCreateWithFlags(&ev_csr, cudaEventDisableTiming);
        cudaFuncSetAttribute((const void*)gemm_f16_kernel<false, false, 128>,
                             cudaFuncAttributeMaxDynamicSharedMemorySize, SMEM128);
        cudaFuncSetAttribute((const void*)gemm_f16_kernel<true, true, 128>,
                             cudaFuncAttributeMaxDynamicSharedMemorySize, SMEM128);
        cudaFuncSetAttribute((const void*)gemm_f16_kernel<true, false, 256>,
                             cudaFuncAttributeMaxDynamicSharedMemorySize, SMEM256);
    }

    const int ROW_BLKS = NN / 8;             // 6250
    const int E_BLKS   = (NEDGES + 255) / 256;
    const int N_BLKS   = (NN + 255) / 256;

    // Fork CSR build onto side stream (needs only ei/ew)
    detect_idx_kernel<<<1, 256>>>((const int*)ei);
    cudaEventRecord(ev_fork, 0);
    cudaStreamWaitEvent(s_csr, ev_fork, 0);
    zero_cnt_kernel<<<N_BLKS, 256, 0, s_csr>>>();
    hist_kernel<<<E_BLKS, 256, 0, s_csr>>>(ei);
    scan_partial_kernel<<<SCAN_BLKS, 256, 0, s_csr>>>();
    scan_blocks_kernel<<<1, 256, 0, s_csr>>>();
    scan_final_kernel<<<SCAN_BLKS, 256, 0, s_csr>>>();
    fill_kernel<<<E_BLKS, 256, 0, s_csr>>>(ei, ew);
    cudaEventRecord(ev_csr, s_csr);

    // Main stream: weight transposes (tiny), lin1, first LN stats
    transpose_w_kernel<<<dim3(HID / 32, IN_C / 32, 1), 256>>>(lin1_w, wt1, IN_C, HID);
    transpose_w_kernel<<<dim3(GC / 32, GC / 32, 8), 256>>>(conv_w, wtc, GC, GC);
    transpose_w_kernel<<<dim3(2, HID / 32, 1), 256>>>(lin2_w, wt2, HID, OUT_C);

    gemm_f16_kernel<false, false, 128><<<dim3(296, 2), 256, SMEM128>>>(
        x, IN_C, wt1, lin1_b, h, HID, NN, HID, nullptr, nullptr);
    ln_stats_kernel<<<ROW_BLKS, 256>>>(h, GC);

    // Join: gathers need the CSR
    cudaStreamWaitEvent(0, ev_csr, 0);

    for (int l = 0; l < NLAYERS; l++) {
        for (int g = 0; g < NGROUPS; g++) {
            int in_ofs  = (g == 0) ? GC : 0;
            int out_ofs = g * GC;
            int bidx = l * NGROUPS + g;
            bool last = (bidx == NLAYERS * NGROUPS - 1);

            gemm_f16_kernel<true, true, 128><<<dim3(296, 1), 256, SMEM128>>>(
                h + in_ofs, HID, wtc + (size_t)bidx * GC * GC, nullptr,
                z, GC, NN, GC,
                norm_g + (size_t)bidx * GC, norm_b + (size_t)bidx * GC);
            if (last)
                gather_kernel<true><<<ROW_BLKS, 256>>>(z, conv_b + (size_t)bidx * GC, h, out_ofs);
            else
                gather_kernel<false><<<ROW_BLKS, 256>>>(z, conv_b + (size_t)bidx * GC, h, out_ofs);
        }
    }

    // lin2 on tensor cores with fused final LN+ReLU (256-wide stats from last gather)
    gemm_f16_kernel<true, false, 256><<<dim3(148, 1), 256, SMEM256>>>(
        h, HID, wt2, lin2_b, out, OUT_C, NN, OUT_C, fnorm_g, fnorm_b);
}